// round 1
// baseline (speedup 1.0000x reference)
#include <cuda_runtime.h>
#include <cuda_bf16.h>
#include <math.h>

// ===== Problem constants =====
#define BB   32
#define SS   197      // tokens incl CLS
#define NTOK 196      // fixations per image
#define DD   768
#define NHH  12
#define HDD  64
#define FF   3072
#define LLAY 12
#define NLAB 1000
#define MROWS (BB*SS)     // 6304
#define MPAT  (BB*NTOK)   // 6272
#define BHN   (BB*NHH)    // 384

// ===== Scratch (device globals; no allocation allowed) =====
__device__ float g_patches[MPAT * DD];
__device__ float g_x[MROWS * DD];
__device__ float g_h[MROWS * DD];
__device__ float g_qkv[MROWS * 3 * DD];
__device__ float g_scores[(size_t)BHN * SS * SS];
__device__ float g_o[MROWS * DD];
__device__ float g_m[MROWS * FF];
__device__ float g_pwt[DD * DD];
__device__ float g_cls[BB * DD];

// ===== Helpers =====
__device__ __forceinline__ float block_reduce_sum(float v, float* red) {
    int tid = threadIdx.x;
    red[tid] = v; __syncthreads();
    #pragma unroll
    for (int s = 128; s > 0; s >>= 1) {
        if (tid < s) red[tid] += red[tid + s];
        __syncthreads();
    }
    float r = red[0]; __syncthreads();
    return r;
}

// ===== Fixation gather: patches[B*N, 768] (layout c*256 + i*16 + j) =====
__global__ __launch_bounds__(256) void gather_kernel(
    const float* __restrict__ px, const int* __restrict__ fix,
    float* __restrict__ patches)
{
    int t = blockIdx.x * 256 + threadIdx.x;
    if (t >= MPAT * DD) return;
    int d = t % DD;
    int row = t / DD;
    int b = row / NTOK, n = row % NTOK;
    int fx = fix[(b * NTOK + n) * 2 + 0];
    int fy = fix[(b * NTOK + n) * 2 + 1];
    int c = d >> 8;
    int rem = d & 255;
    int i = rem >> 4, j = rem & 15;
    bool valid = (fx >= 0) && (fy >= 0);
    int top  = min(max(fy - 8, 0), 224 - 16);
    int left = min(max(fx - 8, 0), 224 - 16);
    float v = 0.f;
    if (valid)
        v = px[(((size_t)b * 3 + c) * 224 + (top + i)) * 224 + (left + j)];
    patches[t] = v;
}

// ===== 768x768 transpose (patch_w [D, CPP] -> [CPP, D]) =====
__global__ void transpose_kernel(const float* __restrict__ in, float* __restrict__ out) {
    __shared__ float t[32][33];
    int x0 = blockIdx.x * 32, y0 = blockIdx.y * 32;
    for (int i = threadIdx.y; i < 32; i += 8)
        t[i][threadIdx.x] = in[(size_t)(y0 + i) * DD + x0 + threadIdx.x];
    __syncthreads();
    for (int i = threadIdx.y; i < 32; i += 8)
        out[(size_t)(x0 + i) * DD + y0 + threadIdx.x] = t[threadIdx.x][i];
}

// ===== CLS row init: x[b,0,:] = cls_token + pos_emb[0] =====
__global__ __launch_bounds__(256) void cls_init_kernel(
    const float* __restrict__ cls_token, const float* __restrict__ pos,
    float* __restrict__ x)
{
    int t = blockIdx.x * 256 + threadIdx.x;
    if (t >= BB * DD) return;
    int b = t / DD, d = t % DD;
    x[(size_t)b * SS * DD + d] = cls_token[d] + pos[d];
}

// ===== SGEMM: C[M,N] = A[M,K] @ B[K,N] (+ epilogues) =====
// 64x64 tile, K-step 16, 256 threads, 4x4 microtile
#define EPI_BIAS  0
#define EPI_RES   1
#define EPI_GELU  2
#define EPI_PATCH 3

__global__ __launch_bounds__(256) void sgemm_kernel(
    const float* __restrict__ A, const float* __restrict__ B,
    float* __restrict__ C, int M, int N, int K,
    const float* __restrict__ bias, const float* __restrict__ pos, int mode)
{
    __shared__ float As[16][64];
    __shared__ float Bs[16][64];
    int tid = threadIdx.x;
    int tx = tid & 15, ty = tid >> 4;
    int m0 = blockIdx.y * 64;
    int n0 = blockIdx.x * 64;
    float acc[4][4] = {};

    int ar  = tid >> 2;           // 0..63
    int ac4 = (tid & 3) * 4;      // 0,4,8,12
    int kr  = tid >> 4;           // 0..15
    int bc4 = (tid & 15) * 4;     // 0..60

    for (int k0 = 0; k0 < K; k0 += 16) {
        float4 av = make_float4(0.f, 0.f, 0.f, 0.f);
        if (m0 + ar < M)
            av = *(const float4*)(A + (size_t)(m0 + ar) * K + k0 + ac4);
        As[ac4 + 0][ar] = av.x; As[ac4 + 1][ar] = av.y;
        As[ac4 + 2][ar] = av.z; As[ac4 + 3][ar] = av.w;
        float4 bv = *(const float4*)(B + (size_t)(k0 + kr) * N + n0 + bc4);
        *(float4*)&Bs[kr][bc4] = bv;
        __syncthreads();
        #pragma unroll
        for (int k = 0; k < 16; k++) {
            float4 a = *(const float4*)&As[k][ty * 4];
            float4 b = *(const float4*)&Bs[k][tx * 4];
            acc[0][0] += a.x * b.x; acc[0][1] += a.x * b.y; acc[0][2] += a.x * b.z; acc[0][3] += a.x * b.w;
            acc[1][0] += a.y * b.x; acc[1][1] += a.y * b.y; acc[1][2] += a.y * b.z; acc[1][3] += a.y * b.w;
            acc[2][0] += a.z * b.x; acc[2][1] += a.z * b.y; acc[2][2] += a.z * b.z; acc[2][3] += a.z * b.w;
            acc[3][0] += a.w * b.x; acc[3][1] += a.w * b.y; acc[3][2] += a.w * b.z; acc[3][3] += a.w * b.w;
        }
        __syncthreads();
    }

    #pragma unroll
    for (int i = 0; i < 4; i++) {
        int r = m0 + ty * 4 + i;
        if (r >= M) continue;
        #pragma unroll
        for (int j = 0; j < 4; j++) {
            int c = n0 + tx * 4 + j;
            if (c >= N) continue;
            float v = acc[i][j] + bias[c];
            if (mode == EPI_BIAS) {
                C[(size_t)r * N + c] = v;
            } else if (mode == EPI_RES) {
                C[(size_t)r * N + c] += v;
            } else if (mode == EPI_GELU) {
                C[(size_t)r * N + c] = 0.5f * v * (1.f + erff(v * 0.70710678118654752f));
            } else { // EPI_PATCH: remap row b*197+n+1, add pos_emb[n+1]
                int b = r / NTOK, n = r % NTOK;
                int orow = b * SS + n + 1;
                C[(size_t)orow * DD + c] = v + pos[(size_t)(n + 1) * DD + c];
            }
        }
    }
}

// ===== LayerNorm: out_row[blockIdx.x] = LN(x_row[blockIdx.x*rowstep]) =====
__global__ __launch_bounds__(256) void ln_kernel(
    const float* __restrict__ x, float* __restrict__ o,
    const float* __restrict__ g, const float* __restrict__ bb, int rowstep)
{
    __shared__ float red[256];
    const float* xr = x + (size_t)blockIdx.x * rowstep * DD;
    float* orow = o + (size_t)blockIdx.x * DD;
    int tid = threadIdx.x;
    float v0 = xr[tid], v1 = xr[tid + 256], v2 = xr[tid + 512];
    float mu = block_reduce_sum(v0 + v1 + v2, red) * (1.f / 768.f);
    float d0 = v0 - mu, d1 = v1 - mu, d2 = v2 - mu;
    float var = block_reduce_sum(d0 * d0 + d1 * d1 + d2 * d2, red) * (1.f / 768.f);
    float rs = rsqrtf(var + 1e-12f);
    orow[tid]       = d0 * rs * g[tid]       + bb[tid];
    orow[tid + 256] = d1 * rs * g[tid + 256] + bb[tid + 256];
    orow[tid + 512] = d2 * rs * g[tid + 512] + bb[tid + 512];
}

// ===== Attention scores: S[bh,q,k] = (Q . K) * 0.125 =====
__global__ __launch_bounds__(256) void scores_kernel(
    const float* __restrict__ qkv, float* __restrict__ scores)
{
    int bh = blockIdx.z;
    int b = bh / NHH, h = bh % NHH;
    int qt = blockIdx.y * 32, kt = blockIdx.x * 32;
    __shared__ float Qs[64][32];
    __shared__ float Ks[64][32];
    const float* qb = qkv + (size_t)b * SS * (3 * DD) + h * HDD;
    const float* kb = qb + DD;
    int tid = threadIdx.x;
    for (int t = tid; t < 512; t += 256) {
        int r = t >> 4;
        int c4 = (t & 15) * 4;
        float4 qv = make_float4(0.f, 0.f, 0.f, 0.f);
        float4 kv = make_float4(0.f, 0.f, 0.f, 0.f);
        if (qt + r < SS) qv = *(const float4*)(qb + (size_t)(qt + r) * (3 * DD) + c4);
        if (kt + r < SS) kv = *(const float4*)(kb + (size_t)(kt + r) * (3 * DD) + c4);
        Qs[c4 + 0][r] = qv.x; Qs[c4 + 1][r] = qv.y; Qs[c4 + 2][r] = qv.z; Qs[c4 + 3][r] = qv.w;
        Ks[c4 + 0][r] = kv.x; Ks[c4 + 1][r] = kv.y; Ks[c4 + 2][r] = kv.z; Ks[c4 + 3][r] = kv.w;
    }
    __syncthreads();
    int tx = tid & 15, ty = tid >> 4;
    float acc[2][2] = {};
    #pragma unroll
    for (int k = 0; k < 64; k++) {
        float2 a = *(const float2*)&Qs[k][ty * 2];
        float2 c = *(const float2*)&Ks[k][tx * 2];
        acc[0][0] += a.x * c.x; acc[0][1] += a.x * c.y;
        acc[1][0] += a.y * c.x; acc[1][1] += a.y * c.y;
    }
    #pragma unroll
    for (int i = 0; i < 2; i++) {
        int qi = qt + ty * 2 + i;
        if (qi >= SS) continue;
        #pragma unroll
        for (int j = 0; j < 2; j++) {
            int kj = kt + tx * 2 + j;
            if (kj >= SS) continue;
            scores[((size_t)bh * SS + qi) * SS + kj] = acc[i][j] * 0.125f;
        }
    }
}

// ===== Row softmax over 197, warp per row =====
__global__ __launch_bounds__(256) void softmax_kernel(float* __restrict__ s, int rows) {
    int w = (blockIdx.x * 256 + threadIdx.x) >> 5;
    int lane = threadIdx.x & 31;
    if (w >= rows) return;
    float* row = s + (size_t)w * SS;
    float mx = -1e30f;
    for (int j = lane; j < SS; j += 32) mx = fmaxf(mx, row[j]);
    #pragma unroll
    for (int o = 16; o > 0; o >>= 1) mx = fmaxf(mx, __shfl_xor_sync(0xffffffff, mx, o));
    float sum = 0.f;
    for (int j = lane; j < SS; j += 32) {
        float e = expf(row[j] - mx);
        row[j] = e; sum += e;
    }
    #pragma unroll
    for (int o = 16; o > 0; o >>= 1) sum += __shfl_xor_sync(0xffffffff, sum, o);
    float inv = 1.f / sum;
    for (int j = lane; j < SS; j += 32) row[j] *= inv;
}

// ===== AV: o[b,q,h*64+d] = sum_j P[bh,q,j] * V[b,j,h,d] =====
__global__ __launch_bounds__(256) void av_kernel(
    const float* __restrict__ qkv, const float* __restrict__ scores,
    float* __restrict__ o)
{
    int bh = blockIdx.y;
    int b = bh / NHH, h = bh % NHH;
    int qt = blockIdx.x * 32;
    __shared__ float Vs[112][64];
    __shared__ float Ps[32][112];
    int tid = threadIdx.x;
    int d = tid & 63, qg = tid >> 6;
    float acc[8] = {};
    const float* vb = qkv + (size_t)b * SS * (3 * DD) + 2 * DD + h * HDD;
    const float* sb = scores + (size_t)bh * SS * SS;

    for (int j0 = 0; j0 < SS; j0 += 112) {
        int jn = min(112, SS - j0);
        for (int t = tid; t < jn * 16; t += 256) {
            int jr = t >> 4, c4 = (t & 15) * 4;
            *(float4*)&Vs[jr][c4] = *(const float4*)(vb + (size_t)(j0 + jr) * (3 * DD) + c4);
        }
        for (int t = tid; t < 32 * 112; t += 256) {
            int qr = t / 112, jc = t % 112;
            float v = 0.f;
            if (qt + qr < SS && jc < jn) v = sb[(size_t)(qt + qr) * SS + j0 + jc];
            Ps[qr][jc] = v;
        }
        __syncthreads();
        #pragma unroll
        for (int qs = 0; qs < 8; qs++) {
            int q = qs * 4 + qg;
            float a = acc[qs];
            #pragma unroll 4
            for (int j = 0; j < jn; j++)
                a += Ps[q][j] * Vs[j][d];
            acc[qs] = a;
        }
        __syncthreads();
    }
    #pragma unroll
    for (int qs = 0; qs < 8; qs++) {
        int q = qt + qs * 4 + qg;
        if (q < SS)
            o[((size_t)b * SS + q) * DD + h * HDD + d] = acc[qs];
    }
}

// ===== Classifier head: warp per (b, label) =====
__global__ __launch_bounds__(256) void cls_head_kernel(
    const float* __restrict__ xc, const float* __restrict__ w,
    const float* __restrict__ bias, float* __restrict__ out)
{
    int wid = (blockIdx.x * 256 + threadIdx.x) >> 5;
    int lane = threadIdx.x & 31;
    if (wid >= BB * NLAB) return;
    int b = wid / NLAB, n = wid % NLAB;
    const float* xr = xc + (size_t)b * DD;
    const float* wr = w + (size_t)n * DD;
    float s = 0.f;
    for (int k = lane * 4; k < DD; k += 128) {
        float4 a = *(const float4*)(xr + k);
        float4 c = *(const float4*)(wr + k);
        s += a.x * c.x + a.y * c.y + a.z * c.z + a.w * c.w;
    }
    #pragma unroll
    for (int o = 16; o > 0; o >>= 1) s += __shfl_xor_sync(0xffffffff, s, o);
    if (lane == 0) out[(size_t)b * NLAB + n] = s + bias[n];
}

// ===== Host orchestration =====
extern "C" void kernel_launch(void* const* d_in, const int* in_sizes, int n_in,
                              void* d_out, int out_size) {
    const float* px        = (const float*)d_in[0];
    const int*   fix       = (const int*)  d_in[1];
    const float* patch_w   = (const float*)d_in[2];
    const float* patch_b   = (const float*)d_in[3];
    const float* cls_token = (const float*)d_in[4];
    const float* pos_emb   = (const float*)d_in[5];
    const float* ln1_g     = (const float*)d_in[6];
    const float* ln1_b     = (const float*)d_in[7];
    const float* wqkv      = (const float*)d_in[8];
    const float* bqkv      = (const float*)d_in[9];
    const float* wo        = (const float*)d_in[10];
    const float* bo        = (const float*)d_in[11];
    const float* ln2_g     = (const float*)d_in[12];
    const float* ln2_b     = (const float*)d_in[13];
    const float* w1        = (const float*)d_in[14];
    const float* b1        = (const float*)d_in[15];
    const float* w2        = (const float*)d_in[16];
    const float* b2        = (const float*)d_in[17];
    const float* lnf_g     = (const float*)d_in[18];
    const float* lnf_b     = (const float*)d_in[19];
    const float* cls_w     = (const float*)d_in[20];
    const float* cls_b     = (const float*)d_in[21];
    float* out = (float*)d_out;

    float *x, *h, *qkv, *sc, *o, *m, *patches, *pwt, *clsb;
    cudaGetSymbolAddress((void**)&patches, g_patches);
    cudaGetSymbolAddress((void**)&x,   g_x);
    cudaGetSymbolAddress((void**)&h,   g_h);
    cudaGetSymbolAddress((void**)&qkv, g_qkv);
    cudaGetSymbolAddress((void**)&sc,  g_scores);
    cudaGetSymbolAddress((void**)&o,   g_o);
    cudaGetSymbolAddress((void**)&m,   g_m);
    cudaGetSymbolAddress((void**)&pwt, g_pwt);
    cudaGetSymbolAddress((void**)&clsb,g_cls);

    // Patch pipeline
    gather_kernel<<<(MPAT * DD + 255) / 256, 256>>>(px, fix, patches);
    transpose_kernel<<<dim3(24, 24), dim3(32, 8)>>>(patch_w, pwt);
    cls_init_kernel<<<(BB * DD + 255) / 256, 256>>>(cls_token, pos_emb, x);
    sgemm_kernel<<<dim3(DD / 64, (MPAT + 63) / 64), 256>>>(
        patches, pwt, x, MPAT, DD, DD, patch_b, pos_emb, EPI_PATCH);

    const int gM = (MROWS + 63) / 64;  // 99
    for (int l = 0; l < LLAY; l++) {
        ln_kernel<<<MROWS, 256>>>(x, h, ln1_g + l * DD, ln1_b + l * DD, 1);
        sgemm_kernel<<<dim3(3 * DD / 64, gM), 256>>>(
            h, wqkv + (size_t)l * DD * 3 * DD, qkv, MROWS, 3 * DD, DD,
            bqkv + (size_t)l * 3 * DD, nullptr, EPI_BIAS);
        scores_kernel<<<dim3(7, 7, BHN), 256>>>(qkv, sc);
        softmax_kernel<<<(BHN * SS * 32 + 255) / 256, 256>>>(sc, BHN * SS);
        av_kernel<<<dim3(7, BHN), 256>>>(qkv, sc, o);
        sgemm_kernel<<<dim3(DD / 64, gM), 256>>>(
            o, wo + (size_t)l * DD * DD, x, MROWS, DD, DD,
            bo + (size_t)l * DD, nullptr, EPI_RES);
        ln_kernel<<<MROWS, 256>>>(x, h, ln2_g + l * DD, ln2_b + l * DD, 1);
        sgemm_kernel<<<dim3(FF / 64, gM), 256>>>(
            h, w1 + (size_t)l * DD * FF, m, MROWS, FF, DD,
            b1 + (size_t)l * FF, nullptr, EPI_GELU);
        sgemm_kernel<<<dim3(DD / 64, gM), 256>>>(
            m, w2 + (size_t)l * FF * DD, x, MROWS, DD, FF,
            b2 + (size_t)l * DD, nullptr, EPI_RES);
    }

    // Final LN on CLS rows only, then classifier
    ln_kernel<<<BB, 256>>>(x, clsb, lnf_g, lnf_b, SS);
    cls_head_kernel<<<(BB * NLAB * 32 + 255) / 256, 256>>>(clsb, cls_w, cls_b, out);
}

// round 2
// speedup vs baseline: 1.0012x; 1.0012x over previous
#include <cuda_runtime.h>
#include <cuda_bf16.h>
#include <math.h>

// ===== Problem constants =====
#define BB   32
#define SS   197      // tokens incl CLS
#define NTOK 196      // fixations per image
#define DD   768
#define NHH  12
#define HDD  64
#define FF   3072
#define LLAY 12
#define NLAB 1000
#define MROWS (BB*SS)     // 6304
#define MPAT  (BB*NTOK)   // 6272
#define BHN   (BB*NHH)    // 384

// ===== Scratch (device globals; no allocation allowed) =====
__device__ float g_patches[MPAT * DD];
__device__ float g_x[MROWS * DD];
__device__ float g_h[MROWS * DD];
__device__ float g_qkv[MROWS * 3 * DD];
__device__ float g_scores[(size_t)BHN * SS * SS];
__device__ float g_o[MROWS * DD];
__device__ float g_m[MROWS * FF];
__device__ float g_pwt[DD * DD];
__device__ float g_cls[BB * DD];

// ===== Helpers =====
__device__ __forceinline__ float block_reduce_sum(float v, float* red) {
    int tid = threadIdx.x;
    red[tid] = v; __syncthreads();
    #pragma unroll
    for (int s = 128; s > 0; s >>= 1) {
        if (tid < s) red[tid] += red[tid + s];
        __syncthreads();
    }
    float r = red[0]; __syncthreads();
    return r;
}

// ===== Fixation gather: patches[B*N, 768] (layout c*256 + i*16 + j) =====
__global__ __launch_bounds__(256) void gather_kernel(
    const float* __restrict__ px, const int* __restrict__ fix,
    float* __restrict__ patches)
{
    int t = blockIdx.x * 256 + threadIdx.x;
    if (t >= MPAT * DD) return;
    int d = t % DD;
    int row = t / DD;
    int b = row / NTOK, n = row % NTOK;
    int fx = fix[(b * NTOK + n) * 2 + 0];
    int fy = fix[(b * NTOK + n) * 2 + 1];
    int c = d >> 8;
    int rem = d & 255;
    int i = rem >> 4, j = rem & 15;
    bool valid = (fx >= 0) && (fy >= 0);
    int top  = min(max(fy - 8, 0), 224 - 16);
    int left = min(max(fx - 8, 0), 224 - 16);
    float v = 0.f;
    if (valid)
        v = px[(((size_t)b * 3 + c) * 224 + (top + i)) * 224 + (left + j)];
    patches[t] = v;
}

// ===== 768x768 transpose (patch_w [D, CPP] -> [CPP, D]) =====
__global__ void transpose_kernel(const float* __restrict__ in, float* __restrict__ out) {
    __shared__ float t[32][33];
    int x0 = blockIdx.x * 32, y0 = blockIdx.y * 32;
    for (int i = threadIdx.y; i < 32; i += 8)
        t[i][threadIdx.x] = in[(size_t)(y0 + i) * DD + x0 + threadIdx.x];
    __syncthreads();
    for (int i = threadIdx.y; i < 32; i += 8)
        out[(size_t)(x0 + i) * DD + y0 + threadIdx.x] = t[threadIdx.x][i];
}

// ===== CLS row init: x[b,0,:] = cls_token + pos_emb[0] =====
__global__ __launch_bounds__(256) void cls_init_kernel(
    const float* __restrict__ cls_token, const float* __restrict__ pos,
    float* __restrict__ x)
{
    int t = blockIdx.x * 256 + threadIdx.x;
    if (t >= BB * DD) return;
    int b = t / DD, d = t % DD;
    x[(size_t)b * SS * DD + d] = cls_token[d] + pos[d];
}

// ===== SGEMM: C[M,N] = A[M,K] @ B[K,N] (+ epilogues) =====
// 64x64 tile, K-step 16, 256 threads, 4x4 microtile
#define EPI_BIAS  0
#define EPI_RES   1
#define EPI_GELU  2
#define EPI_PATCH 3

__global__ __launch_bounds__(256) void sgemm_kernel(
    const float* __restrict__ A, const float* __restrict__ B,
    float* __restrict__ C, int M, int N, int K,
    const float* __restrict__ bias, const float* __restrict__ pos, int mode)
{
    __shared__ float As[16][64];
    __shared__ float Bs[16][64];
    int tid = threadIdx.x;
    int tx = tid & 15, ty = tid >> 4;
    int m0 = blockIdx.y * 64;
    int n0 = blockIdx.x * 64;
    float acc[4][4] = {};

    int ar  = tid >> 2;           // 0..63
    int ac4 = (tid & 3) * 4;      // 0,4,8,12
    int kr  = tid >> 4;           // 0..15
    int bc4 = (tid & 15) * 4;     // 0..60

    for (int k0 = 0; k0 < K; k0 += 16) {
        float4 av = make_float4(0.f, 0.f, 0.f, 0.f);
        if (m0 + ar < M)
            av = *(const float4*)(A + (size_t)(m0 + ar) * K + k0 + ac4);
        As[ac4 + 0][ar] = av.x; As[ac4 + 1][ar] = av.y;
        As[ac4 + 2][ar] = av.z; As[ac4 + 3][ar] = av.w;
        float4 bv = *(const float4*)(B + (size_t)(k0 + kr) * N + n0 + bc4);
        *(float4*)&Bs[kr][bc4] = bv;
        __syncthreads();
        #pragma unroll
        for (int k = 0; k < 16; k++) {
            float4 a = *(const float4*)&As[k][ty * 4];
            float4 b = *(const float4*)&Bs[k][tx * 4];
            acc[0][0] += a.x * b.x; acc[0][1] += a.x * b.y; acc[0][2] += a.x * b.z; acc[0][3] += a.x * b.w;
            acc[1][0] += a.y * b.x; acc[1][1] += a.y * b.y; acc[1][2] += a.y * b.z; acc[1][3] += a.y * b.w;
            acc[2][0] += a.z * b.x; acc[2][1] += a.z * b.y; acc[2][2] += a.z * b.z; acc[2][3] += a.z * b.w;
            acc[3][0] += a.w * b.x; acc[3][1] += a.w * b.y; acc[3][2] += a.w * b.z; acc[3][3] += a.w * b.w;
        }
        __syncthreads();
    }

    #pragma unroll
    for (int i = 0; i < 4; i++) {
        int r = m0 + ty * 4 + i;
        if (r >= M) continue;
        #pragma unroll
        for (int j = 0; j < 4; j++) {
            int c = n0 + tx * 4 + j;
            if (c >= N) continue;
            float v = acc[i][j] + bias[c];
            if (mode == EPI_BIAS) {
                C[(size_t)r * N + c] = v;
            } else if (mode == EPI_RES) {
                C[(size_t)r * N + c] += v;
            } else if (mode == EPI_GELU) {
                C[(size_t)r * N + c] = 0.5f * v * (1.f + erff(v * 0.70710678118654752f));
            } else { // EPI_PATCH: remap row b*197+n+1, add pos_emb[n+1]
                int b = r / NTOK, n = r % NTOK;
                int orow = b * SS + n + 1;
                C[(size_t)orow * DD + c] = v + pos[(size_t)(n + 1) * DD + c];
            }
        }
    }
}

// ===== LayerNorm: out_row[blockIdx.x] = LN(x_row[blockIdx.x*rowstep]) =====
__global__ __launch_bounds__(256) void ln_kernel(
    const float* __restrict__ x, float* __restrict__ o,
    const float* __restrict__ g, const float* __restrict__ bb, int rowstep)
{
    __shared__ float red[256];
    const float* xr = x + (size_t)blockIdx.x * rowstep * DD;
    float* orow = o + (size_t)blockIdx.x * DD;
    int tid = threadIdx.x;
    float v0 = xr[tid], v1 = xr[tid + 256], v2 = xr[tid + 512];
    float mu = block_reduce_sum(v0 + v1 + v2, red) * (1.f / 768.f);
    float d0 = v0 - mu, d1 = v1 - mu, d2 = v2 - mu;
    float var = block_reduce_sum(d0 * d0 + d1 * d1 + d2 * d2, red) * (1.f / 768.f);
    float rs = rsqrtf(var + 1e-12f);
    orow[tid]       = d0 * rs * g[tid]       + bb[tid];
    orow[tid + 256] = d1 * rs * g[tid + 256] + bb[tid + 256];
    orow[tid + 512] = d2 * rs * g[tid + 512] + bb[tid + 512];
}

// ===== Attention scores: S[bh,q,k] = (Q . K) * 0.125 =====
__global__ __launch_bounds__(256) void scores_kernel(
    const float* __restrict__ qkv, float* __restrict__ scores)
{
    int bh = blockIdx.z;
    int b = bh / NHH, h = bh % NHH;
    int qt = blockIdx.y * 32, kt = blockIdx.x * 32;
    __shared__ float Qs[64][32];
    __shared__ float Ks[64][32];
    const float* qb = qkv + (size_t)b * SS * (3 * DD) + h * HDD;
    const float* kb = qb + DD;
    int tid = threadIdx.x;
    for (int t = tid; t < 512; t += 256) {
        int r = t >> 4;
        int c4 = (t & 15) * 4;
        float4 qv = make_float4(0.f, 0.f, 0.f, 0.f);
        float4 kv = make_float4(0.f, 0.f, 0.f, 0.f);
        if (qt + r < SS) qv = *(const float4*)(qb + (size_t)(qt + r) * (3 * DD) + c4);
        if (kt + r < SS) kv = *(const float4*)(kb + (size_t)(kt + r) * (3 * DD) + c4);
        Qs[c4 + 0][r] = qv.x; Qs[c4 + 1][r] = qv.y; Qs[c4 + 2][r] = qv.z; Qs[c4 + 3][r] = qv.w;
        Ks[c4 + 0][r] = kv.x; Ks[c4 + 1][r] = kv.y; Ks[c4 + 2][r] = kv.z; Ks[c4 + 3][r] = kv.w;
    }
    __syncthreads();
    int tx = tid & 15, ty = tid >> 4;
    float acc[2][2] = {};
    #pragma unroll
    for (int k = 0; k < 64; k++) {
        float2 a = *(const float2*)&Qs[k][ty * 2];
        float2 c = *(const float2*)&Ks[k][tx * 2];
        acc[0][0] += a.x * c.x; acc[0][1] += a.x * c.y;
        acc[1][0] += a.y * c.x; acc[1][1] += a.y * c.y;
    }
    #pragma unroll
    for (int i = 0; i < 2; i++) {
        int qi = qt + ty * 2 + i;
        if (qi >= SS) continue;
        #pragma unroll
        for (int j = 0; j < 2; j++) {
            int kj = kt + tx * 2 + j;
            if (kj >= SS) continue;
            scores[((size_t)bh * SS + qi) * SS + kj] = acc[i][j] * 0.125f;
        }
    }
}

// ===== Row softmax over 197, warp per row =====
__global__ __launch_bounds__(256) void softmax_kernel(float* __restrict__ s, int rows) {
    int w = (blockIdx.x * 256 + threadIdx.x) >> 5;
    int lane = threadIdx.x & 31;
    if (w >= rows) return;
    float* row = s + (size_t)w * SS;
    float mx = -1e30f;
    for (int j = lane; j < SS; j += 32) mx = fmaxf(mx, row[j]);
    #pragma unroll
    for (int o = 16; o > 0; o >>= 1) mx = fmaxf(mx, __shfl_xor_sync(0xffffffff, mx, o));
    float sum = 0.f;
    for (int j = lane; j < SS; j += 32) {
        float e = expf(row[j] - mx);
        row[j] = e; sum += e;
    }
    #pragma unroll
    for (int o = 16; o > 0; o >>= 1) sum += __shfl_xor_sync(0xffffffff, sum, o);
    float inv = 1.f / sum;
    for (int j = lane; j < SS; j += 32) row[j] *= inv;
}

// ===== AV: o[b,q,h*64+d] = sum_j P[bh,q,j] * V[b,j,h,d] =====
__global__ __launch_bounds__(256) void av_kernel(
    const float* __restrict__ qkv, const float* __restrict__ scores,
    float* __restrict__ o)
{
    int bh = blockIdx.y;
    int b = bh / NHH, h = bh % NHH;
    int qt = blockIdx.x * 32;
    __shared__ float Vs[112][64];
    __shared__ float Ps[32][112];
    int tid = threadIdx.x;
    int d = tid & 63, qg = tid >> 6;
    float acc[8] = {};
    const float* vb = qkv + (size_t)b * SS * (3 * DD) + 2 * DD + h * HDD;
    const float* sb = scores + (size_t)bh * SS * SS;

    for (int j0 = 0; j0 < SS; j0 += 112) {
        int jn = min(112, SS - j0);
        for (int t = tid; t < jn * 16; t += 256) {
            int jr = t >> 4, c4 = (t & 15) * 4;
            *(float4*)&Vs[jr][c4] = *(const float4*)(vb + (size_t)(j0 + jr) * (3 * DD) + c4);
        }
        for (int t = tid; t < 32 * 112; t += 256) {
            int qr = t / 112, jc = t % 112;
            float v = 0.f;
            if (qt + qr < SS && jc < jn) v = sb[(size_t)(qt + qr) * SS + j0 + jc];
            Ps[qr][jc] = v;
        }
        __syncthreads();
        #pragma unroll
        for (int qs = 0; qs < 8; qs++) {
            int q = qs * 4 + qg;
            float a = acc[qs];
            #pragma unroll 4
            for (int j = 0; j < jn; j++)
                a += Ps[q][j] * Vs[j][d];
            acc[qs] = a;
        }
        __syncthreads();
    }
    #pragma unroll
    for (int qs = 0; qs < 8; qs++) {
        int q = qt + qs * 4 + qg;
        if (q < SS)
            o[((size_t)b * SS + q) * DD + h * HDD + d] = acc[qs];
    }
}

// ===== Classifier head: warp per (b, label) =====
__global__ __launch_bounds__(256) void cls_head_kernel(
    const float* __restrict__ xc, const float* __restrict__ w,
    const float* __restrict__ bias, float* __restrict__ out)
{
    int wid = (blockIdx.x * 256 + threadIdx.x) >> 5;
    int lane = threadIdx.x & 31;
    if (wid >= BB * NLAB) return;
    int b = wid / NLAB, n = wid % NLAB;
    const float* xr = xc + (size_t)b * DD;
    const float* wr = w + (size_t)n * DD;
    float s = 0.f;
    for (int k = lane * 4; k < DD; k += 128) {
        float4 a = *(const float4*)(xr + k);
        float4 c = *(const float4*)(wr + k);
        s += a.x * c.x + a.y * c.y + a.z * c.z + a.w * c.w;
    }
    #pragma unroll
    for (int o = 16; o > 0; o >>= 1) s += __shfl_xor_sync(0xffffffff, s, o);
    if (lane == 0) out[(size_t)b * NLAB + n] = s + bias[n];
}

// ===== Host orchestration =====
extern "C" void kernel_launch(void* const* d_in, const int* in_sizes, int n_in,
                              void* d_out, int out_size) {
    const float* px        = (const float*)d_in[0];
    const int*   fix       = (const int*)  d_in[1];
    const float* patch_w   = (const float*)d_in[2];
    const float* patch_b   = (const float*)d_in[3];
    const float* cls_token = (const float*)d_in[4];
    const float* pos_emb   = (const float*)d_in[5];
    const float* ln1_g     = (const float*)d_in[6];
    const float* ln1_b     = (const float*)d_in[7];
    const float* wqkv      = (const float*)d_in[8];
    const float* bqkv      = (const float*)d_in[9];
    const float* wo        = (const float*)d_in[10];
    const float* bo        = (const float*)d_in[11];
    const float* ln2_g     = (const float*)d_in[12];
    const float* ln2_b     = (const float*)d_in[13];
    const float* w1        = (const float*)d_in[14];
    const float* b1        = (const float*)d_in[15];
    const float* w2        = (const float*)d_in[16];
    const float* b2        = (const float*)d_in[17];
    const float* lnf_g     = (const float*)d_in[18];
    const float* lnf_b     = (const float*)d_in[19];
    const float* cls_w     = (const float*)d_in[20];
    const float* cls_b     = (const float*)d_in[21];
    float* out = (float*)d_out;

    float *x, *h, *qkv, *sc, *o, *m, *patches, *pwt, *clsb;
    cudaGetSymbolAddress((void**)&patches, g_patches);
    cudaGetSymbolAddress((void**)&x,   g_x);
    cudaGetSymbolAddress((void**)&h,   g_h);
    cudaGetSymbolAddress((void**)&qkv, g_qkv);
    cudaGetSymbolAddress((void**)&sc,  g_scores);
    cudaGetSymbolAddress((void**)&o,   g_o);
    cudaGetSymbolAddress((void**)&m,   g_m);
    cudaGetSymbolAddress((void**)&pwt, g_pwt);
    cudaGetSymbolAddress((void**)&clsb,g_cls);

    // Patch pipeline
    gather_kernel<<<(MPAT * DD + 255) / 256, 256>>>(px, fix, patches);
    transpose_kernel<<<dim3(24, 24), dim3(32, 8)>>>(patch_w, pwt);
    cls_init_kernel<<<(BB * DD + 255) / 256, 256>>>(cls_token, pos_emb, x);
    sgemm_kernel<<<dim3(DD / 64, (MPAT + 63) / 64), 256>>>(
        patches, pwt, x, MPAT, DD, DD, patch_b, pos_emb, EPI_PATCH);

    const int gM = (MROWS + 63) / 64;  // 99
    for (int l = 0; l < LLAY; l++) {
        ln_kernel<<<MROWS, 256>>>(x, h, ln1_g + l * DD, ln1_b + l * DD, 1);
        sgemm_kernel<<<dim3(3 * DD / 64, gM), 256>>>(
            h, wqkv + (size_t)l * DD * 3 * DD, qkv, MROWS, 3 * DD, DD,
            bqkv + (size_t)l * 3 * DD, nullptr, EPI_BIAS);
        scores_kernel<<<dim3(7, 7, BHN), 256>>>(qkv, sc);
        softmax_kernel<<<(BHN * SS * 32 + 255) / 256, 256>>>(sc, BHN * SS);
        av_kernel<<<dim3(7, BHN), 256>>>(qkv, sc, o);
        sgemm_kernel<<<dim3(DD / 64, gM), 256>>>(
            o, wo + (size_t)l * DD * DD, x, MROWS, DD, DD,
            bo + (size_t)l * DD, nullptr, EPI_RES);
        ln_kernel<<<MROWS, 256>>>(x, h, ln2_g + l * DD, ln2_b + l * DD, 1);
        sgemm_kernel<<<dim3(FF / 64, gM), 256>>>(
            h, w1 + (size_t)l * DD * FF, m, MROWS, FF, DD,
            b1 + (size_t)l * FF, nullptr, EPI_GELU);
        sgemm_kernel<<<dim3(DD / 64, gM), 256>>>(
            m, w2 + (size_t)l * FF * DD, x, MROWS, DD, FF,
            b2 + (size_t)l * DD, nullptr, EPI_RES);
    }

    // Final LN on CLS rows only, then classifier
    ln_kernel<<<BB, 256>>>(x, clsb, lnf_g, lnf_b, SS);
    cls_head_kernel<<<(BB * NLAB * 32 + 255) / 256, 256>>>(clsb, cls_w, cls_b, out);
}

// round 4
// speedup vs baseline: 2.1637x; 2.1612x over previous
#include <cuda_runtime.h>
#include <cuda_bf16.h>
#include <math.h>
#include <stdint.h>

#define BB   32
#define SS   197
#define NTOK 196
#define DD   768
#define NHH  12
#define HDD  64
#define FF   3072
#define LLAY 12
#define NLAB 1000
#define MROWS (BB*SS)
#define MPAT  (BB*NTOK)
#define BHN   (BB*NHH)

// ===== Scratch =====
__device__ __nv_bfloat16 g_ph[MPAT * DD], g_pl[MPAT * DD];
__device__ __nv_bfloat16 g_hh[MROWS * DD], g_hl[MROWS * DD];
__device__ __nv_bfloat16 g_oh[MROWS * DD], g_ol[MROWS * DD];
__device__ __nv_bfloat16 g_mh[MROWS * FF], g_ml[MROWS * FF];
__device__ __nv_bfloat16 g_wqkvh[LLAY*3*DD*DD], g_wqkvl[LLAY*3*DD*DD];
__device__ __nv_bfloat16 g_woh[LLAY*DD*DD],     g_wol[LLAY*DD*DD];
__device__ __nv_bfloat16 g_w1h[LLAY*FF*DD],     g_w1l[LLAY*FF*DD];
__device__ __nv_bfloat16 g_w2h[LLAY*DD*FF],     g_w2l[LLAY*DD*FF];
__device__ __nv_bfloat16 g_pwh[DD * DD], g_pwl[DD * DD];
__device__ float g_x[MROWS * DD];
__device__ float g_qkv[MROWS * 3 * DD];
__device__ float g_scores[(size_t)BHN * SS * SS];
__device__ float g_cls[BB * DD];

// ===== helpers =====
__device__ __forceinline__ uint32_t s2u(const void* p) {
    uint32_t a;
    asm("{ .reg .u64 t; cvta.to.shared.u64 t, %1; cvt.u32.u64 %0, t; }" : "=r"(a) : "l"(p));
    return a;
}
__device__ __forceinline__ void split_bf16(float v, __nv_bfloat16& h, __nv_bfloat16& l) {
    h = __float2bfloat16(v);
    l = __float2bfloat16(v - __bfloat162float(h));
}
__device__ __forceinline__ void cpa16(uint32_t s, const void* g, int pv) {
    asm volatile("cp.async.cg.shared.global [%0], [%1], 16, %2;"
        :: "r"(s), "l"(g), "r"(pv) : "memory");
}
#define CP_COMMIT() asm volatile("cp.async.commit_group;" ::: "memory")
#define CP_WAIT0()  asm volatile("cp.async.wait_group 0;" ::: "memory")

__device__ __forceinline__ void ldm4(uint32_t* f, uint32_t a) {
    asm volatile("ldmatrix.sync.aligned.m8n8.x4.shared.b16 {%0,%1,%2,%3}, [%4];"
        : "=r"(f[0]), "=r"(f[1]), "=r"(f[2]), "=r"(f[3]) : "r"(a));
}
__device__ __forceinline__ void mma16(float* c, const uint32_t* a, uint32_t b0, uint32_t b1) {
    asm volatile("mma.sync.aligned.m16n8k16.row.col.f32.bf16.bf16.f32 "
        "{%0,%1,%2,%3},{%4,%5,%6,%7},{%8,%9},{%0,%1,%2,%3};"
        : "+f"(c[0]), "+f"(c[1]), "+f"(c[2]), "+f"(c[3])
        : "r"(a[0]), "r"(a[1]), "r"(a[2]), "r"(a[3]), "r"(b0), "r"(b1));
}

// ===== Weight transpose+split: W[z][K][N] fp32 -> oh/ol[z][N][K] bf16 =====
__global__ void wconv_t_kernel(const float* __restrict__ W,
    __nv_bfloat16* __restrict__ oh, __nv_bfloat16* __restrict__ ol, int K, int N)
{
    __shared__ float t[32][33];
    size_t ls = (size_t)blockIdx.z * K * N;
    const float* w = W + ls;
    int k0 = blockIdx.y * 32, n0 = blockIdx.x * 32;
    int tx = threadIdx.x, ty = threadIdx.y;
    for (int i = ty; i < 32; i += 8)
        t[i][tx] = w[(size_t)(k0 + i) * N + n0 + tx];
    __syncthreads();
    for (int i = ty; i < 32; i += 8) {
        __nv_bfloat16 h, l; split_bf16(t[tx][i], h, l);
        size_t o = ls + (size_t)(n0 + i) * K + k0 + tx;
        oh[o] = h; ol[o] = l;
    }
}

__global__ __launch_bounds__(256) void wconv_kernel(const float* __restrict__ W,
    __nv_bfloat16* __restrict__ oh, __nv_bfloat16* __restrict__ ol, int n)
{
    int t = blockIdx.x * 256 + threadIdx.x;
    if (t >= n) return;
    __nv_bfloat16 h, l; split_bf16(W[t], h, l);
    oh[t] = h; ol[t] = l;
}

// ===== Fixation gather -> bf16 hi/lo =====
__global__ __launch_bounds__(256) void gather_kernel(
    const float* __restrict__ px, const int* __restrict__ fix,
    __nv_bfloat16* __restrict__ ph, __nv_bfloat16* __restrict__ pl)
{
    int t = blockIdx.x * 256 + threadIdx.x;
    if (t >= MPAT * DD) return;
    int d = t % DD, row = t / DD;
    int b = row / NTOK, n = row % NTOK;
    int fx = fix[(b * NTOK + n) * 2 + 0];
    int fy = fix[(b * NTOK + n) * 2 + 1];
    int c = d >> 8, rem = d & 255, i = rem >> 4, j = rem & 15;
    bool valid = (fx >= 0) && (fy >= 0);
    int top  = min(max(fy - 8, 0), 208);
    int left = min(max(fx - 8, 0), 208);
    float v = 0.f;
    if (valid) v = px[(((size_t)b * 3 + c) * 224 + (top + i)) * 224 + (left + j)];
    __nv_bfloat16 h, l; split_bf16(v, h, l);
    ph[t] = h; pl[t] = l;
}

__global__ __launch_bounds__(256) void cls_init_kernel(
    const float* __restrict__ ct, const float* __restrict__ pos, float* __restrict__ x)
{
    int t = blockIdx.x * 256 + threadIdx.x;
    if (t >= BB * DD) return;
    x[(size_t)(t / DD) * SS * DD + (t % DD)] = ct[t % DD] + pos[t % DD];
}

// ===== HMMA split-bf16 GEMM: C[M,N] = A[M,K] @ B[N,K]^T =====
// CTA 128x128, BK=32, 256 threads, warp tile 64x32 (2x4 warps)
#define RPB 80            // smem row pitch bytes (40 bf16)
#define OAH 0
#define OAL 10240
#define OBH 20480
#define OBL 30720
#define STG 40960
#define GSMEM (2*STG)

#define EPI_BIAS  0
#define EPI_RES   1
#define EPI_GELU  2
#define EPI_PATCH 3

__device__ __forceinline__ void load_stage(uint32_t sbase,
    const __nv_bfloat16* Ah, const __nv_bfloat16* Al,
    const __nv_bfloat16* Bh, const __nv_bfloat16* Bl,
    int m0, int n0, int K, int k0, int Mv, int tid)
{
    #pragma unroll
    for (int i = 0; i < 2; i++) {
        int c = tid + i * 256;
        int row = c >> 2, k8 = (c & 3) * 8;
        uint32_t soff = (uint32_t)(row * RPB + k8 * 2);
        int ra = m0 + row;
        int pa = (ra < Mv) ? 16 : 0;
        int rc = ra < Mv ? ra : (Mv - 1);
        size_t ga = (size_t)rc * K + k0 + k8;
        cpa16(sbase + OAH + soff, Ah + ga, pa);
        cpa16(sbase + OAL + soff, Al + ga, pa);
        size_t gb = (size_t)(n0 + row) * K + k0 + k8;
        cpa16(sbase + OBH + soff, Bh + gb, 16);
        cpa16(sbase + OBL + soff, Bl + gb, 16);
    }
}

__global__ __launch_bounds__(256) void gemm_hmma(
    const __nv_bfloat16* __restrict__ Ah, const __nv_bfloat16* __restrict__ Al,
    const __nv_bfloat16* __restrict__ Bh, const __nv_bfloat16* __restrict__ Bl,
    float* __restrict__ Cf, __nv_bfloat16* __restrict__ Coh, __nv_bfloat16* __restrict__ Col,
    int Mv, int N, int K,
    const float* __restrict__ bias, const float* __restrict__ pos, int mode)
{
    extern __shared__ char smem[];
    uint32_t sb = s2u(smem);
    int tid = threadIdx.x, wid = tid >> 5, lane = tid & 31;
    const int m0 = blockIdx.y * 128;
    const int n0 = blockIdx.x * 128;
    const int wm = wid & 1, wn = wid >> 1;

    float acc[4][4][4];
    #pragma unroll
    for (int a = 0; a < 4; a++)
        #pragma unroll
        for (int b = 0; b < 4; b++)
            #pragma unroll
            for (int d = 0; d < 4; d++) acc[a][b][d] = 0.f;

    const int nk = K / 32;
    load_stage(sb, Ah, Al, Bh, Bl, m0, n0, K, 0, Mv, tid);
    CP_COMMIT();

    // lane-dependent ldmatrix address components
    int arow = wm * 64 + (lane & 15);
    int acol = (lane >> 4) * 8;                 // + kc
    int brow = wn * 32 + (lane & 7) + ((lane >> 4) << 3);
    int bcol = ((lane >> 3) & 1) * 8;           // + kc

    for (int kt = 0; kt < nk; kt++) {
        CP_WAIT0();
        __syncthreads();
        if (kt + 1 < nk)
            load_stage(sb + ((kt + 1) & 1) * STG, Ah, Al, Bh, Bl, m0, n0, K, (kt + 1) * 32, Mv, tid);
        CP_COMMIT();

        uint32_t cs = sb + (kt & 1) * STG;
        #pragma unroll
        for (int ks = 0; ks < 2; ks++) {
            int kc = ks * 16;
            uint32_t ah[4][4], al4[4][4], bh2[2][4], bl2[2][4];
            uint32_t abase = cs + (uint32_t)(arow * RPB + (acol + kc) * 2);
            #pragma unroll
            for (int mg = 0; mg < 4; mg++) {
                ldm4(ah[mg],  abase + OAH + mg * 16 * RPB);
                ldm4(al4[mg], abase + OAL + mg * 16 * RPB);
            }
            uint32_t bbase = cs + (uint32_t)(brow * RPB + (bcol + kc) * 2);
            #pragma unroll
            for (int p = 0; p < 2; p++) {
                ldm4(bh2[p], bbase + OBH + p * 16 * RPB);
                ldm4(bl2[p], bbase + OBL + p * 16 * RPB);
            }
            #pragma unroll
            for (int mg = 0; mg < 4; mg++) {
                #pragma unroll
                for (int ng = 0; ng < 4; ng++) {
                    uint32_t b0h = bh2[ng >> 1][(ng & 1) * 2], b1h = bh2[ng >> 1][(ng & 1) * 2 + 1];
                    uint32_t b0l = bl2[ng >> 1][(ng & 1) * 2], b1l = bl2[ng >> 1][(ng & 1) * 2 + 1];
                    mma16(acc[mg][ng], ah[mg],  b0h, b1h);
                    mma16(acc[mg][ng], ah[mg],  b0l, b1l);
                    mma16(acc[mg][ng], al4[mg], b0h, b1h);
                }
            }
        }
        __syncthreads();
    }

    // Epilogue
    #pragma unroll
    for (int mg = 0; mg < 4; mg++) {
        #pragma unroll
        for (int ng = 0; ng < 4; ng++) {
            int col = n0 + wn * 32 + ng * 8 + 2 * (lane & 3);
            float2 bz = *(const float2*)(bias + col);
            #pragma unroll
            for (int half = 0; half < 2; half++) {
                int row = m0 + wm * 64 + mg * 16 + (lane >> 2) + half * 8;
                if (row >= Mv) continue;
                float v0 = acc[mg][ng][half * 2 + 0] + bz.x;
                float v1 = acc[mg][ng][half * 2 + 1] + bz.y;
                if (mode == EPI_BIAS) {
                    *(float2*)(Cf + (size_t)row * N + col) = make_float2(v0, v1);
                } else if (mode == EPI_RES) {
                    float2 o = *(const float2*)(Cf + (size_t)row * N + col);
                    o.x += v0; o.y += v1;
                    *(float2*)(Cf + (size_t)row * N + col) = o;
                } else if (mode == EPI_GELU) {
                    v0 = 0.5f * v0 * (1.f + erff(v0 * 0.70710678118654752f));
                    v1 = 0.5f * v1 * (1.f + erff(v1 * 0.70710678118654752f));
                    __nv_bfloat16 h0, l0, h1, l1;
                    split_bf16(v0, h0, l0); split_bf16(v1, h1, l1);
                    uint32_t uh = ((uint32_t)__bfloat16_as_ushort(h1) << 16) | __bfloat16_as_ushort(h0);
                    uint32_t ul = ((uint32_t)__bfloat16_as_ushort(l1) << 16) | __bfloat16_as_ushort(l0);
                    *(uint32_t*)(Coh + (size_t)row * N + col) = uh;
                    *(uint32_t*)(Col + (size_t)row * N + col) = ul;
                } else { // EPI_PATCH
                    int b = row / NTOK, n = row % NTOK;
                    float2 pz = *(const float2*)(pos + (size_t)(n + 1) * DD + col);
                    v0 += pz.x; v1 += pz.y;
                    *(float2*)(Cf + (size_t)(b * SS + n + 1) * DD + col) = make_float2(v0, v1);
                }
            }
        }
    }
}

// ===== LayerNorm =====
__device__ __forceinline__ float block_reduce_sum(float v, float* red) {
    int tid = threadIdx.x;
    red[tid] = v; __syncthreads();
    #pragma unroll
    for (int s = 128; s > 0; s >>= 1) { if (tid < s) red[tid] += red[tid + s]; __syncthreads(); }
    float r = red[0]; __syncthreads();
    return r;
}

__global__ __launch_bounds__(256) void ln_bf16_kernel(
    const float* __restrict__ x, __nv_bfloat16* __restrict__ oh, __nv_bfloat16* __restrict__ ol,
    const float* __restrict__ g, const float* __restrict__ bb)
{
    __shared__ float red[256];
    const float* xr = x + (size_t)blockIdx.x * DD;
    int tid = threadIdx.x;
    float v0 = xr[tid], v1 = xr[tid + 256], v2 = xr[tid + 512];
    float mu = block_reduce_sum(v0 + v1 + v2, red) * (1.f / 768.f);
    float d0 = v0 - mu, d1 = v1 - mu, d2 = v2 - mu;
    float var = block_reduce_sum(d0*d0 + d1*d1 + d2*d2, red) * (1.f / 768.f);
    float rs = rsqrtf(var + 1e-12f);
    size_t base = (size_t)blockIdx.x * DD;
    __nv_bfloat16 h, l;
    split_bf16(d0*rs*g[tid]     + bb[tid],     h, l); oh[base+tid]     = h; ol[base+tid]     = l;
    split_bf16(d1*rs*g[tid+256] + bb[tid+256], h, l); oh[base+tid+256] = h; ol[base+tid+256] = l;
    split_bf16(d2*rs*g[tid+512] + bb[tid+512], h, l); oh[base+tid+512] = h; ol[base+tid+512] = l;
}

__global__ __launch_bounds__(256) void ln_f32_kernel(
    const float* __restrict__ x, float* __restrict__ o,
    const float* __restrict__ g, const float* __restrict__ bb, int rowstep)
{
    __shared__ float red[256];
    const float* xr = x + (size_t)blockIdx.x * rowstep * DD;
    float* orow = o + (size_t)blockIdx.x * DD;
    int tid = threadIdx.x;
    float v0 = xr[tid], v1 = xr[tid + 256], v2 = xr[tid + 512];
    float mu = block_reduce_sum(v0 + v1 + v2, red) * (1.f / 768.f);
    float d0 = v0 - mu, d1 = v1 - mu, d2 = v2 - mu;
    float var = block_reduce_sum(d0*d0 + d1*d1 + d2*d2, red) * (1.f / 768.f);
    float rs = rsqrtf(var + 1e-12f);
    orow[tid]     = d0*rs*g[tid]     + bb[tid];
    orow[tid+256] = d1*rs*g[tid+256] + bb[tid+256];
    orow[tid+512] = d2*rs*g[tid+512] + bb[tid+512];
}

// ===== Attention (fp32) =====
__global__ __launch_bounds__(256) void scores_kernel(
    const float* __restrict__ qkv, float* __restrict__ scores)
{
    int bh = blockIdx.z, b = bh / NHH, h = bh % NHH;
    int qt = blockIdx.y * 32, kt = blockIdx.x * 32;
    __shared__ float Qs[64][32];
    __shared__ float Ks[64][32];
    const float* qb = qkv + (size_t)b * SS * (3*DD) + h * HDD;
    const float* kb = qb + DD;
    int tid = threadIdx.x;
    for (int t = tid; t < 512; t += 256) {
        int r = t >> 4, c4 = (t & 15) * 4;
        float4 qv = make_float4(0,0,0,0), kv = make_float4(0,0,0,0);
        if (qt + r < SS) qv = *(const float4*)(qb + (size_t)(qt + r) * (3*DD) + c4);
        if (kt + r < SS) kv = *(const float4*)(kb + (size_t)(kt + r) * (3*DD) + c4);
        Qs[c4+0][r]=qv.x; Qs[c4+1][r]=qv.y; Qs[c4+2][r]=qv.z; Qs[c4+3][r]=qv.w;
        Ks[c4+0][r]=kv.x; Ks[c4+1][r]=kv.y; Ks[c4+2][r]=kv.z; Ks[c4+3][r]=kv.w;
    }
    __syncthreads();
    int tx = tid & 15, ty = tid >> 4;
    float acc[2][2] = {};
    #pragma unroll
    for (int k = 0; k < 64; k++) {
        float2 a = *(const float2*)&Qs[k][ty*2];
        float2 c = *(const float2*)&Ks[k][tx*2];
        acc[0][0]+=a.x*c.x; acc[0][1]+=a.x*c.y; acc[1][0]+=a.y*c.x; acc[1][1]+=a.y*c.y;
    }
    #pragma unroll
    for (int i = 0; i < 2; i++) {
        int qi = qt + ty*2 + i; if (qi >= SS) continue;
        #pragma unroll
        for (int j = 0; j < 2; j++) {
            int kj = kt + tx*2 + j; if (kj >= SS) continue;
            scores[((size_t)bh * SS + qi) * SS + kj] = acc[i][j] * 0.125f;
        }
    }
}

__global__ __launch_bounds__(256) void softmax_kernel(float* __restrict__ s, int rows) {
    int w = (blockIdx.x * 256 + threadIdx.x) >> 5;
    int lane = threadIdx.x & 31;
    if (w >= rows) return;
    float* row = s + (size_t)w * SS;
    float mx = -1e30f;
    for (int j = lane; j < SS; j += 32) mx = fmaxf(mx, row[j]);
    #pragma unroll
    for (int o = 16; o > 0; o >>= 1) mx = fmaxf(mx, __shfl_xor_sync(0xffffffff, mx, o));
    float sum = 0.f;
    for (int j = lane; j < SS; j += 32) { float e = expf(row[j] - mx); row[j] = e; sum += e; }
    #pragma unroll
    for (int o = 16; o > 0; o >>= 1) sum += __shfl_xor_sync(0xffffffff, sum, o);
    float inv = 1.f / sum;
    for (int j = lane; j < SS; j += 32) row[j] *= inv;
}

__global__ __launch_bounds__(256) void av_kernel(
    const float* __restrict__ qkv, const float* __restrict__ scores,
    __nv_bfloat16* __restrict__ oh, __nv_bfloat16* __restrict__ ol)
{
    int bh = blockIdx.y, b = bh / NHH, h = bh % NHH;
    int qt = blockIdx.x * 32;
    __shared__ float Vs[112][64];
    __shared__ float Ps[32][112];
    int tid = threadIdx.x, d = tid & 63, qg = tid >> 6;
    float acc[8] = {};
    const float* vb = qkv + (size_t)b * SS * (3*DD) + 2*DD + h * HDD;
    const float* sb = scores + (size_t)bh * SS * SS;
    for (int j0 = 0; j0 < SS; j0 += 112) {
        int jn = min(112, SS - j0);
        for (int t = tid; t < jn * 16; t += 256) {
            int jr = t >> 4, c4 = (t & 15) * 4;
            *(float4*)&Vs[jr][c4] = *(const float4*)(vb + (size_t)(j0 + jr) * (3*DD) + c4);
        }
        for (int t = tid; t < 32 * 112; t += 256) {
            int qr = t / 112, jc = t % 112;
            float v = 0.f;
            if (qt + qr < SS && jc < jn) v = sb[(size_t)(qt + qr) * SS + j0 + jc];
            Ps[qr][jc] = v;
        }
        __syncthreads();
        #pragma unroll
        for (int qs = 0; qs < 8; qs++) {
            float a = acc[qs];
            #pragma unroll 4
            for (int j = 0; j < jn; j++) a += Ps[qs*4+qg][j] * Vs[j][d];
            acc[qs] = a;
        }
        __syncthreads();
    }
    #pragma unroll
    for (int qs = 0; qs < 8; qs++) {
        int q = qt + qs*4 + qg;
        if (q < SS) {
            __nv_bfloat16 h2, l2; split_bf16(acc[qs], h2, l2);
            size_t o = ((size_t)b * SS + q) * DD + h * HDD + d;
            oh[o] = h2; ol[o] = l2;
        }
    }
}

__global__ __launch_bounds__(256) void cls_head_kernel(
    const float* __restrict__ xc, const float* __restrict__ w,
    const float* __restrict__ bias, float* __restrict__ out)
{
    int wid = (blockIdx.x * 256 + threadIdx.x) >> 5;
    int lane = threadIdx.x & 31;
    if (wid >= BB * NLAB) return;
    int b = wid / NLAB, n = wid % NLAB;
    const float* xr = xc + (size_t)b * DD;
    const float* wr = w + (size_t)n * DD;
    float s = 0.f;
    for (int k = lane * 4; k < DD; k += 128) {
        float4 a = *(const float4*)(xr + k);
        float4 c = *(const float4*)(wr + k);
        s += a.x*c.x + a.y*c.y + a.z*c.z + a.w*c.w;
    }
    #pragma unroll
    for (int o = 16; o > 0; o >>= 1) s += __shfl_xor_sync(0xffffffff, s, o);
    if (lane == 0) out[(size_t)b * NLAB + n] = s + bias[n];
}

// ===== Host =====
extern "C" void kernel_launch(void* const* d_in, const int* in_sizes, int n_in,
                              void* d_out, int out_size) {
    const float* px      = (const float*)d_in[0];
    const int*   fix     = (const int*)  d_in[1];
    const float* patch_w = (const float*)d_in[2];
    const float* patch_b = (const float*)d_in[3];
    const float* cls_tok = (const float*)d_in[4];
    const float* pos_emb = (const float*)d_in[5];
    const float* ln1_g   = (const float*)d_in[6];
    const float* ln1_b   = (const float*)d_in[7];
    const float* wqkv    = (const float*)d_in[8];
    const float* bqkv    = (const float*)d_in[9];
    const float* wo      = (const float*)d_in[10];
    const float* bo      = (const float*)d_in[11];
    const float* ln2_g   = (const float*)d_in[12];
    const float* ln2_b   = (const float*)d_in[13];
    const float* w1      = (const float*)d_in[14];
    const float* b1      = (const float*)d_in[15];
    const float* w2      = (const float*)d_in[16];
    const float* b2      = (const float*)d_in[17];
    const float* lnf_g   = (const float*)d_in[18];
    const float* lnf_b   = (const float*)d_in[19];
    const float* cls_w   = (const float*)d_in[20];
    const float* cls_b   = (const float*)d_in[21];
    float* out = (float*)d_out;

    __nv_bfloat16 *ph,*pl,*hh,*hl,*oh,*ol,*mh,*ml,*wqh,*wql,*woh,*wol,*w1h,*w1l,*w2h,*w2l,*pwh,*pwl;
    float *x,*qkv,*sc,*clsb;
    cudaGetSymbolAddress((void**)&ph, g_ph);   cudaGetSymbolAddress((void**)&pl, g_pl);
    cudaGetSymbolAddress((void**)&hh, g_hh);   cudaGetSymbolAddress((void**)&hl, g_hl);
    cudaGetSymbolAddress((void**)&oh, g_oh);   cudaGetSymbolAddress((void**)&ol, g_ol);
    cudaGetSymbolAddress((void**)&mh, g_mh);   cudaGetSymbolAddress((void**)&ml, g_ml);
    cudaGetSymbolAddress((void**)&wqh, g_wqkvh); cudaGetSymbolAddress((void**)&wql, g_wqkvl);
    cudaGetSymbolAddress((void**)&woh, g_woh); cudaGetSymbolAddress((void**)&wol, g_wol);
    cudaGetSymbolAddress((void**)&w1h, g_w1h); cudaGetSymbolAddress((void**)&w1l, g_w1l);
    cudaGetSymbolAddress((void**)&w2h, g_w2h); cudaGetSymbolAddress((void**)&w2l, g_w2l);
    cudaGetSymbolAddress((void**)&pwh, g_pwh); cudaGetSymbolAddress((void**)&pwl, g_pwl);
    cudaGetSymbolAddress((void**)&x, g_x);     cudaGetSymbolAddress((void**)&qkv, g_qkv);
    cudaGetSymbolAddress((void**)&sc, g_scores); cudaGetSymbolAddress((void**)&clsb, g_cls);

    cudaFuncSetAttribute(gemm_hmma, cudaFuncAttributeMaxDynamicSharedMemorySize, GSMEM);

    // Weight conversion
    wconv_t_kernel<<<dim3(3*DD/32, DD/32, LLAY), dim3(32,8)>>>(wqkv, wqh, wql, DD, 3*DD);
    wconv_t_kernel<<<dim3(DD/32,   DD/32, LLAY), dim3(32,8)>>>(wo,   woh, wol, DD, DD);
    wconv_t_kernel<<<dim3(FF/32,   DD/32, LLAY), dim3(32,8)>>>(w1,   w1h, w1l, DD, FF);
    wconv_t_kernel<<<dim3(DD/32,   FF/32, LLAY), dim3(32,8)>>>(w2,   w2h, w2l, FF, DD);
    wconv_kernel<<<(DD*DD + 255)/256, 256>>>(patch_w, pwh, pwl, DD*DD);

    gather_kernel<<<(MPAT*DD + 255)/256, 256>>>(px, fix, ph, pl);
    cls_init_kernel<<<(BB*DD + 255)/256, 256>>>(cls_tok, pos_emb, x);
    gemm_hmma<<<dim3(DD/128, MPAT/128), 256, GSMEM>>>(
        ph, pl, pwh, pwl, x, nullptr, nullptr, MPAT, DD, DD, patch_b, pos_emb, EPI_PATCH);

    const int gM = (MROWS + 127) / 128;  // 50
    for (int l = 0; l < LLAY; l++) {
        ln_bf16_kernel<<<MROWS, 256>>>(x, hh, hl, ln1_g + l*DD, ln1_b + l*DD);
        gemm_hmma<<<dim3(3*DD/128, gM), 256, GSMEM>>>(
            hh, hl, wqh + (size_t)l*3*DD*DD, wql + (size_t)l*3*DD*DD,
            qkv, nullptr, nullptr, MROWS, 3*DD, DD, bqkv + (size_t)l*3*DD, nullptr, EPI_BIAS);
        scores_kernel<<<dim3(7, 7, BHN), 256>>>(qkv, sc);
        softmax_kernel<<<(BHN*SS*32 + 255)/256, 256>>>(sc, BHN*SS);
        av_kernel<<<dim3(7, BHN), 256>>>(qkv, sc, oh, ol);
        gemm_hmma<<<dim3(DD/128, gM), 256, GSMEM>>>(
            oh, ol, woh + (size_t)l*DD*DD, wol + (size_t)l*DD*DD,
            x, nullptr, nullptr, MROWS, DD, DD, bo + (size_t)l*DD, nullptr, EPI_RES);
        ln_bf16_kernel<<<MROWS, 256>>>(x, hh, hl, ln2_g + l*DD, ln2_b + l*DD);
        gemm_hmma<<<dim3(FF/128, gM), 256, GSMEM>>>(
            hh, hl, w1h + (size_t)l*FF*DD, w1l + (size_t)l*FF*DD,
            nullptr, mh, ml, MROWS, FF, DD, b1 + (size_t)l*FF, nullptr, EPI_GELU);
        gemm_hmma<<<dim3(DD/128, gM), 256, GSMEM>>>(
            mh, ml, w2h + (size_t)l*DD*FF, w2l + (size_t)l*DD*FF,
            x, nullptr, nullptr, MROWS, DD, FF, b2 + (size_t)l*DD, nullptr, EPI_RES);
    }

    ln_f32_kernel<<<BB, 256>>>(x, clsb, lnf_g, lnf_b, SS);
    cls_head_kernel<<<(BB*NLAB*32 + 255)/256, 256>>>(clsb, cls_w, cls_b, out);
}

// round 5
// speedup vs baseline: 2.5564x; 1.1815x over previous
#include <cuda_runtime.h>
#include <cuda_bf16.h>
#include <math.h>
#include <stdint.h>

#define BB   32
#define SS   197
#define NTOK 196
#define DD   768
#define NHH  12
#define HDD  64
#define FF   3072
#define LLAY 12
#define NLAB 1000
#define MROWS (BB*SS)
#define MPAT  (BB*NTOK)
#define BHN   (BB*NHH)

// ===== Scratch =====
__device__ __nv_bfloat16 g_ph[MPAT * DD], g_pl[MPAT * DD];
__device__ __nv_bfloat16 g_hh[MROWS * DD], g_hl[MROWS * DD];
__device__ __nv_bfloat16 g_oh[MROWS * DD], g_ol[MROWS * DD];
__device__ __nv_bfloat16 g_mh[MROWS * FF], g_ml[MROWS * FF];
__device__ __nv_bfloat16 g_wqkvh[LLAY*3*DD*DD], g_wqkvl[LLAY*3*DD*DD];
__device__ __nv_bfloat16 g_woh[LLAY*DD*DD],     g_wol[LLAY*DD*DD];
__device__ __nv_bfloat16 g_w1h[LLAY*FF*DD],     g_w1l[LLAY*FF*DD];
__device__ __nv_bfloat16 g_w2h[LLAY*DD*FF],     g_w2l[LLAY*DD*FF];
__device__ __nv_bfloat16 g_pwh[DD * DD], g_pwl[DD * DD];
__device__ float g_x[MROWS * DD];
__device__ float g_qkv[MROWS * 3 * DD];
__device__ float g_scores[(size_t)BHN * SS * SS];
__device__ float g_cls[BB * DD];

// ===== helpers =====
__device__ __forceinline__ uint32_t s2u(const void* p) {
    uint32_t a;
    asm("{ .reg .u64 t; cvta.to.shared.u64 t, %1; cvt.u32.u64 %0, t; }" : "=r"(a) : "l"(p));
    return a;
}
__device__ __forceinline__ void split_bf16(float v, __nv_bfloat16& h, __nv_bfloat16& l) {
    h = __float2bfloat16(v);
    l = __float2bfloat16(v - __bfloat162float(h));
}
__device__ __forceinline__ void cpa16(uint32_t s, const void* g) {
    asm volatile("cp.async.cg.shared.global [%0], [%1], 16;"
        :: "r"(s), "l"(g) : "memory");
}
#define CP_COMMIT() asm volatile("cp.async.commit_group;" ::: "memory")
#define CP_WAIT2()  asm volatile("cp.async.wait_group 2;" ::: "memory")

__device__ __forceinline__ void ldm4(uint32_t* f, uint32_t a) {
    asm volatile("ldmatrix.sync.aligned.m8n8.x4.shared.b16 {%0,%1,%2,%3}, [%4];"
        : "=r"(f[0]), "=r"(f[1]), "=r"(f[2]), "=r"(f[3]) : "r"(a));
}
__device__ __forceinline__ void mma16(float* c, const uint32_t* a, uint32_t b0, uint32_t b1) {
    asm volatile("mma.sync.aligned.m16n8k16.row.col.f32.bf16.bf16.f32 "
        "{%0,%1,%2,%3},{%4,%5,%6,%7},{%8,%9},{%0,%1,%2,%3};"
        : "+f"(c[0]), "+f"(c[1]), "+f"(c[2]), "+f"(c[3])
        : "r"(a[0]), "r"(a[1]), "r"(a[2]), "r"(a[3]), "r"(b0), "r"(b1));
}
// XOR swizzle: 64B row pitch, 4x16B chunks, chunk' = chunk ^ ((row>>1)&3)
__device__ __forceinline__ uint32_t swz(int row, int ch) {
    return (uint32_t)(row * 64) + (uint32_t)((ch ^ ((row >> 1) & 3)) << 4);
}

// ===== Weight transpose+split =====
__global__ void wconv_t_kernel(const float* __restrict__ W,
    __nv_bfloat16* __restrict__ oh, __nv_bfloat16* __restrict__ ol, int K, int N)
{
    __shared__ float t[32][33];
    size_t ls = (size_t)blockIdx.z * K * N;
    const float* w = W + ls;
    int k0 = blockIdx.y * 32, n0 = blockIdx.x * 32;
    int tx = threadIdx.x, ty = threadIdx.y;
    for (int i = ty; i < 32; i += 8)
        t[i][tx] = w[(size_t)(k0 + i) * N + n0 + tx];
    __syncthreads();
    for (int i = ty; i < 32; i += 8) {
        __nv_bfloat16 h, l; split_bf16(t[tx][i], h, l);
        size_t o = ls + (size_t)(n0 + i) * K + k0 + tx;
        oh[o] = h; ol[o] = l;
    }
}

__global__ __launch_bounds__(256) void wconv_kernel(const float* __restrict__ W,
    __nv_bfloat16* __restrict__ oh, __nv_bfloat16* __restrict__ ol, int n)
{
    int t = blockIdx.x * 256 + threadIdx.x;
    if (t >= n) return;
    __nv_bfloat16 h, l; split_bf16(W[t], h, l);
    oh[t] = h; ol[t] = l;
}

// ===== Fixation gather -> bf16 hi/lo =====
__global__ __launch_bounds__(256) void gather_kernel(
    const float* __restrict__ px, const int* __restrict__ fix,
    __nv_bfloat16* __restrict__ ph, __nv_bfloat16* __restrict__ pl)
{
    int t = blockIdx.x * 256 + threadIdx.x;
    if (t >= MPAT * DD) return;
    int d = t % DD, row = t / DD;
    int b = row / NTOK, n = row % NTOK;
    int fx = fix[(b * NTOK + n) * 2 + 0];
    int fy = fix[(b * NTOK + n) * 2 + 1];
    int c = d >> 8, rem = d & 255, i = rem >> 4, j = rem & 15;
    bool valid = (fx >= 0) && (fy >= 0);
    int top  = min(max(fy - 8, 0), 208);
    int left = min(max(fx - 8, 0), 208);
    float v = 0.f;
    if (valid) v = px[(((size_t)b * 3 + c) * 224 + (top + i)) * 224 + (left + j)];
    __nv_bfloat16 h, l; split_bf16(v, h, l);
    ph[t] = h; pl[t] = l;
}

__global__ __launch_bounds__(256) void cls_init_kernel(
    const float* __restrict__ ct, const float* __restrict__ pos, float* __restrict__ x)
{
    int t = blockIdx.x * 256 + threadIdx.x;
    if (t >= BB * DD) return;
    x[(size_t)(t / DD) * SS * DD + (t % DD)] = ct[t % DD] + pos[t % DD];
}

// ===== HMMA split-bf16 GEMM: C[M,N] = A[M,K] @ B[N,K]^T =====
// CTA 128x256, BK=32, 512 threads (4x4 warps, warp tile 32x64), 4-stage cp.async
#define OAL 8192
#define OBH 16384
#define OBL 32768
#define STG 49152
#define GSMEM (4*STG)

#define EPI_BIAS  0
#define EPI_RES   1
#define EPI_GELU  2
#define EPI_PATCH 3

__device__ __forceinline__ void load_stage(uint32_t sbase,
    const __nv_bfloat16* Ah, const __nv_bfloat16* Al,
    const __nv_bfloat16* Bh, const __nv_bfloat16* Bl,
    int m0, int n0, int K, int k0, int Mv, int tid)
{
    // A: 128 rows x 4 chunks (hi+lo), 512 threads -> 1 chunk each per buf
    {
        int row = tid >> 2, ch = tid & 3;
        uint32_t so = swz(row, ch);
        int ra = m0 + row;
        int rc = ra < Mv ? ra : (Mv - 1);
        size_t ga = (size_t)rc * K + k0 + ch * 8;
        cpa16(sbase + so, Ah + ga);
        cpa16(sbase + OAL + so, Al + ga);
    }
    // B: 256 rows x 4 chunks (hi+lo), 2 groups
    #pragma unroll
    for (int g = 0; g < 2; g++) {
        int idx = tid + g * 512;
        int row = idx >> 2, ch = idx & 3;
        uint32_t so = swz(row, ch);
        size_t gb = (size_t)(n0 + row) * K + k0 + ch * 8;
        cpa16(sbase + OBH + so, Bh + gb);
        cpa16(sbase + OBL + so, Bl + gb);
    }
}

__global__ __launch_bounds__(512) void gemm_hmma(
    const __nv_bfloat16* __restrict__ Ah, const __nv_bfloat16* __restrict__ Al,
    const __nv_bfloat16* __restrict__ Bh, const __nv_bfloat16* __restrict__ Bl,
    float* __restrict__ Cf, __nv_bfloat16* __restrict__ Coh, __nv_bfloat16* __restrict__ Col,
    int Mv, int N, int K,
    const float* __restrict__ bias, const float* __restrict__ pos, int mode)
{
    extern __shared__ char smem[];
    uint32_t sb = s2u(smem);
    int tid = threadIdx.x, wid = tid >> 5, lane = tid & 31;
    const int m0 = blockIdx.y * 128;
    const int n0 = blockIdx.x * 256;
    const int wm = wid & 3, wn = wid >> 2;   // warp tile 32x64

    float acc[2][8][4];
    #pragma unroll
    for (int a = 0; a < 2; a++)
        #pragma unroll
        for (int b = 0; b < 8; b++)
            #pragma unroll
            for (int d = 0; d < 4; d++) acc[a][b][d] = 0.f;

    const int nk = K / 32;
    #pragma unroll
    for (int s = 0; s < 3; s++) {
        load_stage(sb + s * STG, Ah, Al, Bh, Bl, m0, n0, K, s * 32, Mv, tid);
        CP_COMMIT();
    }

    const int arow_l = (lane & 15);
    const int acsel  = (lane >> 4);            // 0/1
    const int brow_l = (lane & 7) + ((lane >> 4) << 3);
    const int bcsel  = ((lane >> 3) & 1);

    for (int kt = 0; kt < nk; kt++) {
        CP_WAIT2();
        __syncthreads();
        if (kt + 3 < nk)
            load_stage(sb + ((kt + 3) & 3) * STG, Ah, Al, Bh, Bl, m0, n0, K, (kt + 3) * 32, Mv, tid);
        CP_COMMIT();

        uint32_t cs = sb + (kt & 3) * STG;
        #pragma unroll
        for (int ks = 0; ks < 2; ks++) {
            int cbase = ks * 2;  // chunk base for this k16
            uint32_t ah[2][4], al[2][4];
            #pragma unroll
            for (int mg = 0; mg < 2; mg++) {
                int r = wm * 32 + mg * 16 + arow_l;
                uint32_t a_ad = cs + swz(r, cbase + acsel);
                ldm4(ah[mg], a_ad);
                ldm4(al[mg], a_ad + OAL);
            }
            #pragma unroll
            for (int p = 0; p < 4; p++) {
                int br = wn * 64 + p * 16 + brow_l;
                uint32_t b_ad = cs + OBH + swz(br, cbase + bcsel);
                uint32_t bh[4], bl[4];
                ldm4(bh, b_ad);
                ldm4(bl, b_ad + 16384);
                #pragma unroll
                for (int mg = 0; mg < 2; mg++) {
                    #pragma unroll
                    for (int sub = 0; sub < 2; sub++) {
                        float* C = acc[mg][p * 2 + sub];
                        uint32_t b0h = bh[sub * 2], b1h = bh[sub * 2 + 1];
                        uint32_t b0l = bl[sub * 2], b1l = bl[sub * 2 + 1];
                        mma16(C, ah[mg], b0h, b1h);
                        mma16(C, ah[mg], b0l, b1l);
                        mma16(C, al[mg], b0h, b1h);
                    }
                }
            }
        }
        __syncthreads();
    }

    // Epilogue
    #pragma unroll
    for (int mg = 0; mg < 2; mg++) {
        #pragma unroll
        for (int ng = 0; ng < 8; ng++) {
            int col = n0 + wn * 64 + ng * 8 + 2 * (lane & 3);
            float2 bz = *(const float2*)(bias + col);
            #pragma unroll
            for (int half = 0; half < 2; half++) {
                int row = m0 + wm * 32 + mg * 16 + (lane >> 2) + half * 8;
                if (row >= Mv) continue;
                float v0 = acc[mg][ng][half * 2 + 0] + bz.x;
                float v1 = acc[mg][ng][half * 2 + 1] + bz.y;
                if (mode == EPI_BIAS) {
                    *(float2*)(Cf + (size_t)row * N + col) = make_float2(v0, v1);
                } else if (mode == EPI_RES) {
                    float2 o = *(const float2*)(Cf + (size_t)row * N + col);
                    o.x += v0; o.y += v1;
                    *(float2*)(Cf + (size_t)row * N + col) = o;
                } else if (mode == EPI_GELU) {
                    v0 = 0.5f * v0 * (1.f + erff(v0 * 0.70710678118654752f));
                    v1 = 0.5f * v1 * (1.f + erff(v1 * 0.70710678118654752f));
                    __nv_bfloat16 h0, l0, h1, l1;
                    split_bf16(v0, h0, l0); split_bf16(v1, h1, l1);
                    uint32_t uh = ((uint32_t)__bfloat16_as_ushort(h1) << 16) | __bfloat16_as_ushort(h0);
                    uint32_t ul = ((uint32_t)__bfloat16_as_ushort(l1) << 16) | __bfloat16_as_ushort(l0);
                    *(uint32_t*)(Coh + (size_t)row * N + col) = uh;
                    *(uint32_t*)(Col + (size_t)row * N + col) = ul;
                } else { // EPI_PATCH
                    int b = row / NTOK, n = row % NTOK;
                    float2 pz = *(const float2*)(pos + (size_t)(n + 1) * DD + col);
                    v0 += pz.x; v1 += pz.y;
                    *(float2*)(Cf + (size_t)(b * SS + n + 1) * DD + col) = make_float2(v0, v1);
                }
            }
        }
    }
}

// ===== LayerNorm =====
__device__ __forceinline__ float block_reduce_sum(float v, float* red) {
    int tid = threadIdx.x;
    red[tid] = v; __syncthreads();
    #pragma unroll
    for (int s = 128; s > 0; s >>= 1) { if (tid < s) red[tid] += red[tid + s]; __syncthreads(); }
    float r = red[0]; __syncthreads();
    return r;
}

__global__ __launch_bounds__(256) void ln_bf16_kernel(
    const float* __restrict__ x, __nv_bfloat16* __restrict__ oh, __nv_bfloat16* __restrict__ ol,
    const float* __restrict__ g, const float* __restrict__ bb)
{
    __shared__ float red[256];
    const float* xr = x + (size_t)blockIdx.x * DD;
    int tid = threadIdx.x;
    float v0 = xr[tid], v1 = xr[tid + 256], v2 = xr[tid + 512];
    float mu = block_reduce_sum(v0 + v1 + v2, red) * (1.f / 768.f);
    float d0 = v0 - mu, d1 = v1 - mu, d2 = v2 - mu;
    float var = block_reduce_sum(d0*d0 + d1*d1 + d2*d2, red) * (1.f / 768.f);
    float rs = rsqrtf(var + 1e-12f);
    size_t base = (size_t)blockIdx.x * DD;
    __nv_bfloat16 h, l;
    split_bf16(d0*rs*g[tid]     + bb[tid],     h, l); oh[base+tid]     = h; ol[base+tid]     = l;
    split_bf16(d1*rs*g[tid+256] + bb[tid+256], h, l); oh[base+tid+256] = h; ol[base+tid+256] = l;
    split_bf16(d2*rs*g[tid+512] + bb[tid+512], h, l); oh[base+tid+512] = h; ol[base+tid+512] = l;
}

__global__ __launch_bounds__(256) void ln_f32_kernel(
    const float* __restrict__ x, float* __restrict__ o,
    const float* __restrict__ g, const float* __restrict__ bb, int rowstep)
{
    __shared__ float red[256];
    const float* xr = x + (size_t)blockIdx.x * rowstep * DD;
    float* orow = o + (size_t)blockIdx.x * DD;
    int tid = threadIdx.x;
    float v0 = xr[tid], v1 = xr[tid + 256], v2 = xr[tid + 512];
    float mu = block_reduce_sum(v0 + v1 + v2, red) * (1.f / 768.f);
    float d0 = v0 - mu, d1 = v1 - mu, d2 = v2 - mu;
    float var = block_reduce_sum(d0*d0 + d1*d1 + d2*d2, red) * (1.f / 768.f);
    float rs = rsqrtf(var + 1e-12f);
    orow[tid]     = d0*rs*g[tid]     + bb[tid];
    orow[tid+256] = d1*rs*g[tid+256] + bb[tid+256];
    orow[tid+512] = d2*rs*g[tid+512] + bb[tid+512];
}

// ===== Attention (fp32) =====
__global__ __launch_bounds__(256) void scores_kernel(
    const float* __restrict__ qkv, float* __restrict__ scores)
{
    int bh = blockIdx.z, b = bh / NHH, h = bh % NHH;
    int qt = blockIdx.y * 32, kt = blockIdx.x * 32;
    __shared__ float Qs[64][32];
    __shared__ float Ks[64][32];
    const float* qb = qkv + (size_t)b * SS * (3*DD) + h * HDD;
    const float* kb = qb + DD;
    int tid = threadIdx.x;
    for (int t = tid; t < 512; t += 256) {
        int r = t >> 4, c4 = (t & 15) * 4;
        float4 qv = make_float4(0,0,0,0), kv = make_float4(0,0,0,0);
        if (qt + r < SS) qv = *(const float4*)(qb + (size_t)(qt + r) * (3*DD) + c4);
        if (kt + r < SS) kv = *(const float4*)(kb + (size_t)(kt + r) * (3*DD) + c4);
        Qs[c4+0][r]=qv.x; Qs[c4+1][r]=qv.y; Qs[c4+2][r]=qv.z; Qs[c4+3][r]=qv.w;
        Ks[c4+0][r]=kv.x; Ks[c4+1][r]=kv.y; Ks[c4+2][r]=kv.z; Ks[c4+3][r]=kv.w;
    }
    __syncthreads();
    int tx = tid & 15, ty = tid >> 4;
    float acc[2][2] = {};
    #pragma unroll
    for (int k = 0; k < 64; k++) {
        float2 a = *(const float2*)&Qs[k][ty*2];
        float2 c = *(const float2*)&Ks[k][tx*2];
        acc[0][0]+=a.x*c.x; acc[0][1]+=a.x*c.y; acc[1][0]+=a.y*c.x; acc[1][1]+=a.y*c.y;
    }
    #pragma unroll
    for (int i = 0; i < 2; i++) {
        int qi = qt + ty*2 + i; if (qi >= SS) continue;
        #pragma unroll
        for (int j = 0; j < 2; j++) {
            int kj = kt + tx*2 + j; if (kj >= SS) continue;
            scores[((size_t)bh * SS + qi) * SS + kj] = acc[i][j] * 0.125f;
        }
    }
}

__global__ __launch_bounds__(256) void softmax_kernel(float* __restrict__ s, int rows) {
    int w = (blockIdx.x * 256 + threadIdx.x) >> 5;
    int lane = threadIdx.x & 31;
    if (w >= rows) return;
    float* row = s + (size_t)w * SS;
    float mx = -1e30f;
    for (int j = lane; j < SS; j += 32) mx = fmaxf(mx, row[j]);
    #pragma unroll
    for (int o = 16; o > 0; o >>= 1) mx = fmaxf(mx, __shfl_xor_sync(0xffffffff, mx, o));
    float sum = 0.f;
    for (int j = lane; j < SS; j += 32) { float e = expf(row[j] - mx); row[j] = e; sum += e; }
    #pragma unroll
    for (int o = 16; o > 0; o >>= 1) sum += __shfl_xor_sync(0xffffffff, sum, o);
    float inv = 1.f / sum;
    for (int j = lane; j < SS; j += 32) row[j] *= inv;
}

__global__ __launch_bounds__(256) void av_kernel(
    const float* __restrict__ qkv, const float* __restrict__ scores,
    __nv_bfloat16* __restrict__ oh, __nv_bfloat16* __restrict__ ol)
{
    int bh = blockIdx.y, b = bh / NHH, h = bh % NHH;
    int qt = blockIdx.x * 32;
    __shared__ float Vs[112][64];
    __shared__ float Ps[32][112];
    int tid = threadIdx.x, d = tid & 63, qg = tid >> 6;
    float acc[8] = {};
    const float* vb = qkv + (size_t)b * SS * (3*DD) + 2*DD + h * HDD;
    const float* sb = scores + (size_t)bh * SS * SS;
    for (int j0 = 0; j0 < SS; j0 += 112) {
        int jn = min(112, SS - j0);
        for (int t = tid; t < jn * 16; t += 256) {
            int jr = t >> 4, c4 = (t & 15) * 4;
            *(float4*)&Vs[jr][c4] = *(const float4*)(vb + (size_t)(j0 + jr) * (3*DD) + c4);
        }
        for (int t = tid; t < 32 * 112; t += 256) {
            int qr = t / 112, jc = t % 112;
            float v = 0.f;
            if (qt + qr < SS && jc < jn) v = sb[(size_t)(qt + qr) * SS + j0 + jc];
            Ps[qr][jc] = v;
        }
        __syncthreads();
        #pragma unroll
        for (int qs = 0; qs < 8; qs++) {
            float a = acc[qs];
            #pragma unroll 4
            for (int j = 0; j < jn; j++) a += Ps[qs*4+qg][j] * Vs[j][d];
            acc[qs] = a;
        }
        __syncthreads();
    }
    #pragma unroll
    for (int qs = 0; qs < 8; qs++) {
        int q = qt + qs*4 + qg;
        if (q < SS) {
            __nv_bfloat16 h2, l2; split_bf16(acc[qs], h2, l2);
            size_t o = ((size_t)b * SS + q) * DD + h * HDD + d;
            oh[o] = h2; ol[o] = l2;
        }
    }
}

__global__ __launch_bounds__(256) void cls_head_kernel(
    const float* __restrict__ xc, const float* __restrict__ w,
    const float* __restrict__ bias, float* __restrict__ out)
{
    int wid = (blockIdx.x * 256 + threadIdx.x) >> 5;
    int lane = threadIdx.x & 31;
    if (wid >= BB * NLAB) return;
    int b = wid / NLAB, n = wid % NLAB;
    const float* xr = xc + (size_t)b * DD;
    const float* wr = w + (size_t)n * DD;
    float s = 0.f;
    for (int k = lane * 4; k < DD; k += 128) {
        float4 a = *(const float4*)(xr + k);
        float4 c = *(const float4*)(wr + k);
        s += a.x*c.x + a.y*c.y + a.z*c.z + a.w*c.w;
    }
    #pragma unroll
    for (int o = 16; o > 0; o >>= 1) s += __shfl_xor_sync(0xffffffff, s, o);
    if (lane == 0) out[(size_t)b * NLAB + n] = s + bias[n];
}

// ===== Host =====
extern "C" void kernel_launch(void* const* d_in, const int* in_sizes, int n_in,
                              void* d_out, int out_size) {
    const float* px      = (const float*)d_in[0];
    const int*   fix     = (const int*)  d_in[1];
    const float* patch_w = (const float*)d_in[2];
    const float* patch_b = (const float*)d_in[3];
    const float* cls_tok = (const float*)d_in[4];
    const float* pos_emb = (const float*)d_in[5];
    const float* ln1_g   = (const float*)d_in[6];
    const float* ln1_b   = (const float*)d_in[7];
    const float* wqkv    = (const float*)d_in[8];
    const float* bqkv    = (const float*)d_in[9];
    const float* wo      = (const float*)d_in[10];
    const float* bo      = (const float*)d_in[11];
    const float* ln2_g   = (const float*)d_in[12];
    const float* ln2_b   = (const float*)d_in[13];
    const float* w1      = (const float*)d_in[14];
    const float* b1      = (const float*)d_in[15];
    const float* w2      = (const float*)d_in[16];
    const float* b2      = (const float*)d_in[17];
    const float* lnf_g   = (const float*)d_in[18];
    const float* lnf_b   = (const float*)d_in[19];
    const float* cls_w   = (const float*)d_in[20];
    const float* cls_b   = (const float*)d_in[21];
    float* out = (float*)d_out;

    __nv_bfloat16 *ph,*pl,*hh,*hl,*oh,*ol,*mh,*ml,*wqh,*wql,*woh,*wol,*w1h,*w1l,*w2h,*w2l,*pwh,*pwl;
    float *x,*qkv,*sc,*clsb;
    cudaGetSymbolAddress((void**)&ph, g_ph);   cudaGetSymbolAddress((void**)&pl, g_pl);
    cudaGetSymbolAddress((void**)&hh, g_hh);   cudaGetSymbolAddress((void**)&hl, g_hl);
    cudaGetSymbolAddress((void**)&oh, g_oh);   cudaGetSymbolAddress((void**)&ol, g_ol);
    cudaGetSymbolAddress((void**)&mh, g_mh);   cudaGetSymbolAddress((void**)&ml, g_ml);
    cudaGetSymbolAddress((void**)&wqh, g_wqkvh); cudaGetSymbolAddress((void**)&wql, g_wqkvl);
    cudaGetSymbolAddress((void**)&woh, g_woh); cudaGetSymbolAddress((void**)&wol, g_wol);
    cudaGetSymbolAddress((void**)&w1h, g_w1h); cudaGetSymbolAddress((void**)&w1l, g_w1l);
    cudaGetSymbolAddress((void**)&w2h, g_w2h); cudaGetSymbolAddress((void**)&w2l, g_w2l);
    cudaGetSymbolAddress((void**)&pwh, g_pwh); cudaGetSymbolAddress((void**)&pwl, g_pwl);
    cudaGetSymbolAddress((void**)&x, g_x);     cudaGetSymbolAddress((void**)&qkv, g_qkv);
    cudaGetSymbolAddress((void**)&sc, g_scores); cudaGetSymbolAddress((void**)&clsb, g_cls);

    cudaFuncSetAttribute(gemm_hmma, cudaFuncAttributeMaxDynamicSharedMemorySize, GSMEM);

    // Weight conversion
    wconv_t_kernel<<<dim3(3*DD/32, DD/32, LLAY), dim3(32,8)>>>(wqkv, wqh, wql, DD, 3*DD);
    wconv_t_kernel<<<dim3(DD/32,   DD/32, LLAY), dim3(32,8)>>>(wo,   woh, wol, DD, DD);
    wconv_t_kernel<<<dim3(FF/32,   DD/32, LLAY), dim3(32,8)>>>(w1,   w1h, w1l, DD, FF);
    wconv_t_kernel<<<dim3(DD/32,   FF/32, LLAY), dim3(32,8)>>>(w2,   w2h, w2l, FF, DD);
    wconv_kernel<<<(DD*DD + 255)/256, 256>>>(patch_w, pwh, pwl, DD*DD);

    gather_kernel<<<(MPAT*DD + 255)/256, 256>>>(px, fix, ph, pl);
    cls_init_kernel<<<(BB*DD + 255)/256, 256>>>(cls_tok, pos_emb, x);
    gemm_hmma<<<dim3(DD/256, MPAT/128), 512, GSMEM>>>(
        ph, pl, pwh, pwl, x, nullptr, nullptr, MPAT, DD, DD, patch_b, pos_emb, EPI_PATCH);

    const int gM = (MROWS + 127) / 128;  // 50
    for (int l = 0; l < LLAY; l++) {
        ln_bf16_kernel<<<MROWS, 256>>>(x, hh, hl, ln1_g + l*DD, ln1_b + l*DD);
        gemm_hmma<<<dim3(3*DD/256, gM), 512, GSMEM>>>(
            hh, hl, wqh + (size_t)l*3*DD*DD, wql + (size_t)l*3*DD*DD,
            qkv, nullptr, nullptr, MROWS, 3*DD, DD, bqkv + (size_t)l*3*DD, nullptr, EPI_BIAS);
        scores_kernel<<<dim3(7, 7, BHN), 256>>>(qkv, sc);
        softmax_kernel<<<(BHN*SS*32 + 255)/256, 256>>>(sc, BHN*SS);
        av_kernel<<<dim3(7, BHN), 256>>>(qkv, sc, oh, ol);
        gemm_hmma<<<dim3(DD/256, gM), 512, GSMEM>>>(
            oh, ol, woh + (size_t)l*DD*DD, wol + (size_t)l*DD*DD,
            x, nullptr, nullptr, MROWS, DD, DD, bo + (size_t)l*DD, nullptr, EPI_RES);
        ln_bf16_kernel<<<MROWS, 256>>>(x, hh, hl, ln2_g + l*DD, ln2_b + l*DD);
        gemm_hmma<<<dim3(FF/256, gM), 512, GSMEM>>>(
            hh, hl, w1h + (size_t)l*FF*DD, w1l + (size_t)l*FF*DD,
            nullptr, mh, ml, MROWS, FF, DD, b1 + (size_t)l*FF, nullptr, EPI_GELU);
        gemm_hmma<<<dim3(DD/256, gM), 512, GSMEM>>>(
            mh, ml, w2h + (size_t)l*DD*FF, w2l + (size_t)l*DD*FF,
            x, nullptr, nullptr, MROWS, DD, FF, b2 + (size_t)l*DD, nullptr, EPI_RES);
    }

    ln_f32_kernel<<<BB, 256>>>(x, clsb, lnf_g, lnf_b, SS);
    cls_head_kernel<<<(BB*NLAB*32 + 255)/256, 256>>>(clsb, cls_w, cls_b, out);
}

// round 6
// speedup vs baseline: 3.8890x; 1.5212x over previous
#include <cuda_runtime.h>
#include <cuda_bf16.h>
#include <math.h>
#include <stdint.h>

#define BB   32
#define SS   197
#define NTOK 196
#define DD   768
#define NHH  12
#define HDD  64
#define FF   3072
#define LLAY 12
#define NLAB 1000
#define MROWS (BB*SS)
#define MPAT  (BB*NTOK)
#define BHN   (BB*NHH)

// ===== Scratch =====
__device__ __nv_bfloat16 g_ph[MPAT * DD], g_pl[MPAT * DD];
__device__ __nv_bfloat16 g_hh[MROWS * DD], g_hl[MROWS * DD];
__device__ __nv_bfloat16 g_oh[MROWS * DD], g_ol[MROWS * DD];
__device__ __nv_bfloat16 g_mh[MROWS * FF], g_ml[MROWS * FF];
__device__ __nv_bfloat16 g_qkvh[MROWS * 3 * DD], g_qkvl[MROWS * 3 * DD];
__device__ __nv_bfloat16 g_wqkvh[LLAY*3*DD*DD], g_wqkvl[LLAY*3*DD*DD];
__device__ __nv_bfloat16 g_woh[LLAY*DD*DD],     g_wol[LLAY*DD*DD];
__device__ __nv_bfloat16 g_w1h[LLAY*FF*DD],     g_w1l[LLAY*FF*DD];
__device__ __nv_bfloat16 g_w2h[LLAY*DD*FF],     g_w2l[LLAY*DD*FF];
__device__ __nv_bfloat16 g_pwh[DD * DD], g_pwl[DD * DD];
__device__ float g_x[MROWS * DD];
__device__ float g_cls[BB * DD];

// ===== helpers =====
__device__ __forceinline__ uint32_t s2u(const void* p) {
    uint32_t a;
    asm("{ .reg .u64 t; cvta.to.shared.u64 t, %1; cvt.u32.u64 %0, t; }" : "=r"(a) : "l"(p));
    return a;
}
__device__ __forceinline__ void split_bf16(float v, __nv_bfloat16& h, __nv_bfloat16& l) {
    h = __float2bfloat16(v);
    l = __float2bfloat16(v - __bfloat162float(h));
}
__device__ __forceinline__ uint32_t split_pack(float v0, float v1, uint32_t& lo) {
    __nv_bfloat16 h0, l0, h1, l1;
    split_bf16(v0, h0, l0); split_bf16(v1, h1, l1);
    lo = ((uint32_t)__bfloat16_as_ushort(l1) << 16) | __bfloat16_as_ushort(l0);
    return ((uint32_t)__bfloat16_as_ushort(h1) << 16) | __bfloat16_as_ushort(h0);
}
__device__ __forceinline__ void cpa16(uint32_t s, const void* g) {
    asm volatile("cp.async.cg.shared.global [%0], [%1], 16;"
        :: "r"(s), "l"(g) : "memory");
}
#define CP_COMMIT() asm volatile("cp.async.commit_group;" ::: "memory")
#define CP_WAIT2()  asm volatile("cp.async.wait_group 2;" ::: "memory")
#define CP_WAIT1()  asm volatile("cp.async.wait_group 1;" ::: "memory")
#define CP_WAIT0()  asm volatile("cp.async.wait_group 0;" ::: "memory")

__device__ __forceinline__ void ldm4(uint32_t* f, uint32_t a) {
    asm volatile("ldmatrix.sync.aligned.m8n8.x4.shared.b16 {%0,%1,%2,%3}, [%4];"
        : "=r"(f[0]), "=r"(f[1]), "=r"(f[2]), "=r"(f[3]) : "r"(a));
}
__device__ __forceinline__ void ldm4t(uint32_t* f, uint32_t a) {
    asm volatile("ldmatrix.sync.aligned.m8n8.x4.trans.shared.b16 {%0,%1,%2,%3}, [%4];"
        : "=r"(f[0]), "=r"(f[1]), "=r"(f[2]), "=r"(f[3]) : "r"(a));
}
__device__ __forceinline__ void mma16(float* c, const uint32_t* a, uint32_t b0, uint32_t b1) {
    asm volatile("mma.sync.aligned.m16n8k16.row.col.f32.bf16.bf16.f32 "
        "{%0,%1,%2,%3},{%4,%5,%6,%7},{%8,%9},{%0,%1,%2,%3};"
        : "+f"(c[0]), "+f"(c[1]), "+f"(c[2]), "+f"(c[3])
        : "r"(a[0]), "r"(a[1]), "r"(a[2]), "r"(a[3]), "r"(b0), "r"(b1));
}
// 64B-pitch swizzle (GEMM tiles, 4 chunks/row)
__device__ __forceinline__ uint32_t swz(int row, int ch) {
    return (uint32_t)(row * 64) + (uint32_t)((ch ^ ((row >> 1) & 3)) << 4);
}
// 128B-pitch swizzle (attention tiles, 8 chunks/row)
__device__ __forceinline__ uint32_t swz8(int row, int ch) {
    return (uint32_t)(row * 128) + (uint32_t)((ch ^ (row & 7)) << 4);
}

// ===== Weight transpose+split =====
__global__ void wconv_t_kernel(const float* __restrict__ W,
    __nv_bfloat16* __restrict__ oh, __nv_bfloat16* __restrict__ ol, int K, int N)
{
    __shared__ float t[32][33];
    size_t ls = (size_t)blockIdx.z * K * N;
    const float* w = W + ls;
    int k0 = blockIdx.y * 32, n0 = blockIdx.x * 32;
    int tx = threadIdx.x, ty = threadIdx.y;
    for (int i = ty; i < 32; i += 8)
        t[i][tx] = w[(size_t)(k0 + i) * N + n0 + tx];
    __syncthreads();
    for (int i = ty; i < 32; i += 8) {
        __nv_bfloat16 h, l; split_bf16(t[tx][i], h, l);
        size_t o = ls + (size_t)(n0 + i) * K + k0 + tx;
        oh[o] = h; ol[o] = l;
    }
}

__global__ __launch_bounds__(256) void wconv_kernel(const float* __restrict__ W,
    __nv_bfloat16* __restrict__ oh, __nv_bfloat16* __restrict__ ol, int n)
{
    int t = blockIdx.x * 256 + threadIdx.x;
    if (t >= n) return;
    __nv_bfloat16 h, l; split_bf16(W[t], h, l);
    oh[t] = h; ol[t] = l;
}

// ===== Fixation gather -> bf16 hi/lo =====
__global__ __launch_bounds__(256) void gather_kernel(
    const float* __restrict__ px, const int* __restrict__ fix,
    __nv_bfloat16* __restrict__ ph, __nv_bfloat16* __restrict__ pl)
{
    int t = blockIdx.x * 256 + threadIdx.x;
    if (t >= MPAT * DD) return;
    int d = t % DD, row = t / DD;
    int b = row / NTOK, n = row % NTOK;
    int fx = fix[(b * NTOK + n) * 2 + 0];
    int fy = fix[(b * NTOK + n) * 2 + 1];
    int c = d >> 8, rem = d & 255, i = rem >> 4, j = rem & 15;
    bool valid = (fx >= 0) && (fy >= 0);
    int top  = min(max(fy - 8, 0), 208);
    int left = min(max(fx - 8, 0), 208);
    float v = 0.f;
    if (valid) v = px[(((size_t)b * 3 + c) * 224 + (top + i)) * 224 + (left + j)];
    __nv_bfloat16 h, l; split_bf16(v, h, l);
    ph[t] = h; pl[t] = l;
}

__global__ __launch_bounds__(256) void cls_init_kernel(
    const float* __restrict__ ct, const float* __restrict__ pos, float* __restrict__ x)
{
    int t = blockIdx.x * 256 + threadIdx.x;
    if (t >= BB * DD) return;
    x[(size_t)(t / DD) * SS * DD + (t % DD)] = ct[t % DD] + pos[t % DD];
}

// ===== HMMA split-bf16 GEMM =====
#define OAL 8192
#define OBH 16384
#define OBL 32768
#define STG 49152
#define GSMEM (4*STG)

#define EPI_BIAS  0
#define EPI_RES   1
#define EPI_GELU  2
#define EPI_PATCH 3
#define EPI_QKV   4

__device__ __forceinline__ void load_stage(uint32_t sbase,
    const __nv_bfloat16* Ah, const __nv_bfloat16* Al,
    const __nv_bfloat16* Bh, const __nv_bfloat16* Bl,
    int m0, int n0, int K, int k0, int Mv, int tid)
{
    {
        int row = tid >> 2, ch = tid & 3;
        uint32_t so = swz(row, ch);
        int ra = m0 + row;
        int rc = ra < Mv ? ra : (Mv - 1);
        size_t ga = (size_t)rc * K + k0 + ch * 8;
        cpa16(sbase + so, Ah + ga);
        cpa16(sbase + OAL + so, Al + ga);
    }
    #pragma unroll
    for (int g = 0; g < 2; g++) {
        int idx = tid + g * 512;
        int row = idx >> 2, ch = idx & 3;
        uint32_t so = swz(row, ch);
        size_t gb = (size_t)(n0 + row) * K + k0 + ch * 8;
        cpa16(sbase + OBH + so, Bh + gb);
        cpa16(sbase + OBL + so, Bl + gb);
    }
}

__global__ __launch_bounds__(512) void gemm_hmma(
    const __nv_bfloat16* __restrict__ Ah, const __nv_bfloat16* __restrict__ Al,
    const __nv_bfloat16* __restrict__ Bh, const __nv_bfloat16* __restrict__ Bl,
    float* __restrict__ Cf, __nv_bfloat16* __restrict__ Coh, __nv_bfloat16* __restrict__ Col,
    int Mv, int N, int K,
    const float* __restrict__ bias, const float* __restrict__ pos, int mode)
{
    extern __shared__ char smem[];
    uint32_t sb = s2u(smem);
    int tid = threadIdx.x, wid = tid >> 5, lane = tid & 31;
    const int m0 = blockIdx.y * 128;
    const int n0 = blockIdx.x * 256;
    const int wm = wid & 3, wn = wid >> 2;

    float acc[2][8][4];
    #pragma unroll
    for (int a = 0; a < 2; a++)
        #pragma unroll
        for (int b = 0; b < 8; b++)
            #pragma unroll
            for (int d = 0; d < 4; d++) acc[a][b][d] = 0.f;

    const int nk = K / 32;
    #pragma unroll
    for (int s = 0; s < 3; s++) {
        load_stage(sb + s * STG, Ah, Al, Bh, Bl, m0, n0, K, s * 32, Mv, tid);
        CP_COMMIT();
    }

    const int arow_l = (lane & 15);
    const int acsel  = (lane >> 4);
    const int brow_l = (lane & 7) + ((lane >> 4) << 3);
    const int bcsel  = ((lane >> 3) & 1);

    for (int kt = 0; kt < nk; kt++) {
        CP_WAIT2();
        __syncthreads();
        if (kt + 3 < nk)
            load_stage(sb + ((kt + 3) & 3) * STG, Ah, Al, Bh, Bl, m0, n0, K, (kt + 3) * 32, Mv, tid);
        CP_COMMIT();

        uint32_t cs = sb + (kt & 3) * STG;
        #pragma unroll
        for (int ks = 0; ks < 2; ks++) {
            int cbase = ks * 2;
            uint32_t ah[2][4], al[2][4];
            #pragma unroll
            for (int mg = 0; mg < 2; mg++) {
                int r = wm * 32 + mg * 16 + arow_l;
                uint32_t a_ad = cs + swz(r, cbase + acsel);
                ldm4(ah[mg], a_ad);
                ldm4(al[mg], a_ad + OAL);
            }
            #pragma unroll
            for (int p = 0; p < 4; p++) {
                int br = wn * 64 + p * 16 + brow_l;
                uint32_t b_ad = cs + OBH + swz(br, cbase + bcsel);
                uint32_t bh[4], bl[4];
                ldm4(bh, b_ad);
                ldm4(bl, b_ad + 16384);
                #pragma unroll
                for (int mg = 0; mg < 2; mg++) {
                    #pragma unroll
                    for (int sub = 0; sub < 2; sub++) {
                        float* C = acc[mg][p * 2 + sub];
                        uint32_t b0h = bh[sub * 2], b1h = bh[sub * 2 + 1];
                        uint32_t b0l = bl[sub * 2], b1l = bl[sub * 2 + 1];
                        mma16(C, ah[mg], b0h, b1h);
                        mma16(C, ah[mg], b0l, b1l);
                        mma16(C, al[mg], b0h, b1h);
                    }
                }
            }
        }
    }

    // Epilogue
    #pragma unroll
    for (int mg = 0; mg < 2; mg++) {
        #pragma unroll
        for (int ng = 0; ng < 8; ng++) {
            int col = n0 + wn * 64 + ng * 8 + 2 * (lane & 3);
            float2 bz = *(const float2*)(bias + col);
            #pragma unroll
            for (int half = 0; half < 2; half++) {
                int row = m0 + wm * 32 + mg * 16 + (lane >> 2) + half * 8;
                if (row >= Mv) continue;
                float v0 = acc[mg][ng][half * 2 + 0] + bz.x;
                float v1 = acc[mg][ng][half * 2 + 1] + bz.y;
                if (mode == EPI_BIAS) {
                    *(float2*)(Cf + (size_t)row * N + col) = make_float2(v0, v1);
                } else if (mode == EPI_RES) {
                    float2 o = *(const float2*)(Cf + (size_t)row * N + col);
                    o.x += v0; o.y += v1;
                    *(float2*)(Cf + (size_t)row * N + col) = o;
                } else if (mode == EPI_GELU) {
                    v0 = 0.5f * v0 * (1.f + erff(v0 * 0.70710678118654752f));
                    v1 = 0.5f * v1 * (1.f + erff(v1 * 0.70710678118654752f));
                    uint32_t ul;
                    uint32_t uh = split_pack(v0, v1, ul);
                    *(uint32_t*)(Coh + (size_t)row * N + col) = uh;
                    *(uint32_t*)(Col + (size_t)row * N + col) = ul;
                } else if (mode == EPI_QKV) {
                    float sc = (col < DD) ? 0.125f : 1.0f;  // fold attention scale into Q
                    v0 *= sc; v1 *= sc;
                    uint32_t ul;
                    uint32_t uh = split_pack(v0, v1, ul);
                    *(uint32_t*)(Coh + (size_t)row * N + col) = uh;
                    *(uint32_t*)(Col + (size_t)row * N + col) = ul;
                } else { // EPI_PATCH
                    int b = row / NTOK, n = row % NTOK;
                    float2 pz = *(const float2*)(pos + (size_t)(n + 1) * DD + col);
                    v0 += pz.x; v1 += pz.y;
                    *(float2*)(Cf + (size_t)(b * SS + n + 1) * DD + col) = make_float2(v0, v1);
                }
            }
        }
    }
}

// ===== Flash attention (split-bf16 HMMA, full softmax in registers) =====
// Block: (qtile of 128, bh). 256 threads = 8 warps; warp w -> rows qt+w*16..+15.
// SMEM: Qh/Ql [128][64], Kh/Kl [208][64], Vh/Vl [208][64] bf16, 128B rows, swz8.
#define FQH 0
#define FQL 16384
#define FKH 32768
#define FKL 59392
#define FVH 86016
#define FVL 112640
#define FSMEM 139264

__global__ __launch_bounds__(256) void flash_kernel(
    const __nv_bfloat16* __restrict__ QKVh, const __nv_bfloat16* __restrict__ QKVl,
    __nv_bfloat16* __restrict__ Oh, __nv_bfloat16* __restrict__ Ol)
{
    extern __shared__ char smem[];
    uint32_t sb = s2u(smem);
    int tid = threadIdx.x, wid = tid >> 5, lane = tid & 31;
    int bh = blockIdx.y, b = bh / NHH, h = bh % NHH;
    int qt = blockIdx.x * 128;
    const int R3D = 3 * DD;
    const int hoff = h * HDD;

    // ---- loads (Q,K group 0; V group 1) ----
    #pragma unroll
    for (int i = 0; i < 4; i++) {           // Q: 128 rows x 8 chunks
        int idx = tid + i * 256;
        int row = idx >> 3, ch = idx & 7;
        int r = qt + row; if (r > SS - 1) r = SS - 1;
        size_t g = (size_t)(b * SS + r) * R3D + hoff + ch * 8;
        uint32_t so = swz8(row, ch);
        cpa16(sb + FQH + so, QKVh + g);
        cpa16(sb + FQL + so, QKVl + g);
    }
    #pragma unroll
    for (int i = 0; i < 7; i++) {           // K: 208 rows x 8 chunks
        int idx = tid + i * 256;
        if (idx < 1664) {
            int row = idx >> 3, ch = idx & 7;
            int r = row > SS - 1 ? SS - 1 : row;
            size_t g = (size_t)(b * SS + r) * R3D + DD + hoff + ch * 8;
            uint32_t so = swz8(row, ch);
            cpa16(sb + FKH + so, QKVh + g);
            cpa16(sb + FKL + so, QKVl + g);
        }
    }
    CP_COMMIT();
    #pragma unroll
    for (int i = 0; i < 7; i++) {           // V
        int idx = tid + i * 256;
        if (idx < 1664) {
            int row = idx >> 3, ch = idx & 7;
            int r = row > SS - 1 ? SS - 1 : row;
            size_t g = (size_t)(b * SS + r) * R3D + 2 * DD + hoff + ch * 8;
            uint32_t so = swz8(row, ch);
            cpa16(sb + FVH + so, QKVh + g);
            cpa16(sb + FVL + so, QKVl + g);
        }
    }
    CP_COMMIT();
    CP_WAIT1();
    __syncthreads();

    // ---- S = Q K^T (3-term split), 26 n8 tiles in registers ----
    float S[26][4];
    #pragma unroll
    for (int t = 0; t < 26; t++)
        #pragma unroll
        for (int e = 0; e < 4; e++) S[t][e] = 0.f;

    const int arow = lane & 15, acsel = lane >> 4;
    const int brow = (lane & 7) + ((lane >> 4) << 3), bcsel = (lane >> 3) & 1;

    #pragma unroll
    for (int ks = 0; ks < 4; ks++) {
        uint32_t qh[4], ql[4];
        uint32_t qa = sb + FQH + swz8(wid * 16 + arow, ks * 2 + acsel);
        ldm4(qh, qa);
        ldm4(ql, qa + (FQL - FQH));
        #pragma unroll
        for (int p = 0; p < 13; p++) {
            uint32_t ka = sb + FKH + swz8(p * 16 + brow, ks * 2 + bcsel);
            uint32_t kh4[4], kl4[4];
            ldm4(kh4, ka);
            ldm4(kl4, ka + (FKL - FKH));
            #pragma unroll
            for (int sub = 0; sub < 2; sub++) {
                float* C = S[p * 2 + sub];
                mma16(C, qh, kh4[sub * 2], kh4[sub * 2 + 1]);
                mma16(C, qh, kl4[sub * 2], kl4[sub * 2 + 1]);
                mma16(C, ql, kh4[sub * 2], kh4[sub * 2 + 1]);
            }
        }
    }

    // ---- mask j >= 197 ----
    #pragma unroll
    for (int t = 24; t < 26; t++) {
        #pragma unroll
        for (int e = 0; e < 2; e++) {
            int colv = 8 * t + 2 * (lane & 3) + e;
            if (colv >= SS) { S[t][e] = -1e30f; S[t][2 + e] = -1e30f; }
        }
    }

    // ---- softmax in registers (rows r = lane>>2 and r+8) ----
    float m0 = -1e30f, m1 = -1e30f;
    #pragma unroll
    for (int t = 0; t < 26; t++) {
        m0 = fmaxf(m0, fmaxf(S[t][0], S[t][1]));
        m1 = fmaxf(m1, fmaxf(S[t][2], S[t][3]));
    }
    m0 = fmaxf(m0, __shfl_xor_sync(0xffffffff, m0, 1));
    m0 = fmaxf(m0, __shfl_xor_sync(0xffffffff, m0, 2));
    m1 = fmaxf(m1, __shfl_xor_sync(0xffffffff, m1, 1));
    m1 = fmaxf(m1, __shfl_xor_sync(0xffffffff, m1, 2));
    float s0 = 0.f, s1 = 0.f;
    #pragma unroll
    for (int t = 0; t < 26; t++) {
        S[t][0] = __expf(S[t][0] - m0); S[t][1] = __expf(S[t][1] - m0);
        S[t][2] = __expf(S[t][2] - m1); S[t][3] = __expf(S[t][3] - m1);
        s0 += S[t][0] + S[t][1];
        s1 += S[t][2] + S[t][3];
    }
    s0 += __shfl_xor_sync(0xffffffff, s0, 1);
    s0 += __shfl_xor_sync(0xffffffff, s0, 2);
    s1 += __shfl_xor_sync(0xffffffff, s1, 1);
    s1 += __shfl_xor_sync(0xffffffff, s1, 2);
    float inv0 = 1.f / s0, inv1 = 1.f / s1;

    CP_WAIT0();
    __syncthreads();

    // ---- O = P V (3-term split); P a-frags recycled from S C-frags ----
    float Cv[8][4];
    #pragma unroll
    for (int d = 0; d < 8; d++)
        #pragma unroll
        for (int e = 0; e < 4; e++) Cv[d][e] = 0.f;

    const int jr = (lane & 7) + (((lane >> 3) & 1) << 3);
    const int csel = lane >> 4;

    #pragma unroll
    for (int t = 0; t < 13; t++) {
        uint32_t aph[4], apl[4];
        aph[0] = split_pack(S[2*t][0],   S[2*t][1],   apl[0]);
        aph[1] = split_pack(S[2*t][2],   S[2*t][3],   apl[1]);
        aph[2] = split_pack(S[2*t+1][0], S[2*t+1][1], apl[2]);
        aph[3] = split_pack(S[2*t+1][2], S[2*t+1][3], apl[3]);
        #pragma unroll
        for (int dt = 0; dt < 4; dt++) {
            uint32_t va = sb + FVH + swz8(t * 16 + jr, dt * 2 + csel);
            uint32_t vh4[4], vl4[4];
            ldm4t(vh4, va);
            ldm4t(vl4, va + (FVL - FVH));
            #pragma unroll
            for (int sub = 0; sub < 2; sub++) {
                float* C = Cv[dt * 2 + sub];
                mma16(C, aph, vh4[sub * 2], vh4[sub * 2 + 1]);
                mma16(C, aph, vl4[sub * 2], vl4[sub * 2 + 1]);
                mma16(C, apl, vh4[sub * 2], vh4[sub * 2 + 1]);
            }
        }
    }

    // ---- store O (split bf16) ----
    int r0 = qt + wid * 16 + (lane >> 2);
    int r1 = r0 + 8;
    #pragma unroll
    for (int nt = 0; nt < 8; nt++) {
        int col = hoff + nt * 8 + 2 * (lane & 3);
        if (r0 < SS) {
            uint32_t ul;
            uint32_t uh = split_pack(Cv[nt][0] * inv0, Cv[nt][1] * inv0, ul);
            size_t o = (size_t)(b * SS + r0) * DD + col;
            *(uint32_t*)(Oh + o) = uh;
            *(uint32_t*)(Ol + o) = ul;
        }
        if (r1 < SS) {
            uint32_t ul;
            uint32_t uh = split_pack(Cv[nt][2] * inv1, Cv[nt][3] * inv1, ul);
            size_t o = (size_t)(b * SS + r1) * DD + col;
            *(uint32_t*)(Oh + o) = uh;
            *(uint32_t*)(Ol + o) = ul;
        }
    }
}

// ===== LayerNorm =====
__device__ __forceinline__ float block_reduce_sum(float v, float* red) {
    int tid = threadIdx.x;
    red[tid] = v; __syncthreads();
    #pragma unroll
    for (int s = 128; s > 0; s >>= 1) { if (tid < s) red[tid] += red[tid + s]; __syncthreads(); }
    float r = red[0]; __syncthreads();
    return r;
}

__global__ __launch_bounds__(256) void ln_bf16_kernel(
    const float* __restrict__ x, __nv_bfloat16* __restrict__ oh, __nv_bfloat16* __restrict__ ol,
    const float* __restrict__ g, const float* __restrict__ bb)
{
    __shared__ float red[256];
    const float* xr = x + (size_t)blockIdx.x * DD;
    int tid = threadIdx.x;
    float v0 = xr[tid], v1 = xr[tid + 256], v2 = xr[tid + 512];
    float mu = block_reduce_sum(v0 + v1 + v2, red) * (1.f / 768.f);
    float d0 = v0 - mu, d1 = v1 - mu, d2 = v2 - mu;
    float var = block_reduce_sum(d0*d0 + d1*d1 + d2*d2, red) * (1.f / 768.f);
    float rs = rsqrtf(var + 1e-12f);
    size_t base = (size_t)blockIdx.x * DD;
    __nv_bfloat16 h, l;
    split_bf16(d0*rs*g[tid]     + bb[tid],     h, l); oh[base+tid]     = h; ol[base+tid]     = l;
    split_bf16(d1*rs*g[tid+256] + bb[tid+256], h, l); oh[base+tid+256] = h; ol[base+tid+256] = l;
    split_bf16(d2*rs*g[tid+512] + bb[tid+512], h, l); oh[base+tid+512] = h; ol[base+tid+512] = l;
}

__global__ __launch_bounds__(256) void ln_f32_kernel(
    const float* __restrict__ x, float* __restrict__ o,
    const float* __restrict__ g, const float* __restrict__ bb, int rowstep)
{
    __shared__ float red[256];
    const float* xr = x + (size_t)blockIdx.x * rowstep * DD;
    float* orow = o + (size_t)blockIdx.x * DD;
    int tid = threadIdx.x;
    float v0 = xr[tid], v1 = xr[tid + 256], v2 = xr[tid + 512];
    float mu = block_reduce_sum(v0 + v1 + v2, red) * (1.f / 768.f);
    float d0 = v0 - mu, d1 = v1 - mu, d2 = v2 - mu;
    float var = block_reduce_sum(d0*d0 + d1*d1 + d2*d2, red) * (1.f / 768.f);
    float rs = rsqrtf(var + 1e-12f);
    orow[tid]     = d0*rs*g[tid]     + bb[tid];
    orow[tid+256] = d1*rs*g[tid+256] + bb[tid+256];
    orow[tid+512] = d2*rs*g[tid+512] + bb[tid+512];
}

__global__ __launch_bounds__(256) void cls_head_kernel(
    const float* __restrict__ xc, const float* __restrict__ w,
    const float* __restrict__ bias, float* __restrict__ out)
{
    int wid = (blockIdx.x * 256 + threadIdx.x) >> 5;
    int lane = threadIdx.x & 31;
    if (wid >= BB * NLAB) return;
    int b = wid / NLAB, n = wid % NLAB;
    const float* xr = xc + (size_t)b * DD;
    const float* wr = w + (size_t)n * DD;
    float s = 0.f;
    for (int k = lane * 4; k < DD; k += 128) {
        float4 a = *(const float4*)(xr + k);
        float4 c = *(const float4*)(wr + k);
        s += a.x*c.x + a.y*c.y + a.z*c.z + a.w*c.w;
    }
    #pragma unroll
    for (int o = 16; o > 0; o >>= 1) s += __shfl_xor_sync(0xffffffff, s, o);
    if (lane == 0) out[(size_t)b * NLAB + n] = s + bias[n];
}

// ===== Host =====
extern "C" void kernel_launch(void* const* d_in, const int* in_sizes, int n_in,
                              void* d_out, int out_size) {
    const float* px      = (const float*)d_in[0];
    const int*   fix     = (const int*)  d_in[1];
    const float* patch_w = (const float*)d_in[2];
    const float* patch_b = (const float*)d_in[3];
    const float* cls_tok = (const float*)d_in[4];
    const float* pos_emb = (const float*)d_in[5];
    const float* ln1_g   = (const float*)d_in[6];
    const float* ln1_b   = (const float*)d_in[7];
    const float* wqkv    = (const float*)d_in[8];
    const float* bqkv    = (const float*)d_in[9];
    const float* wo      = (const float*)d_in[10];
    const float* bo      = (const float*)d_in[11];
    const float* ln2_g   = (const float*)d_in[12];
    const float* ln2_b   = (const float*)d_in[13];
    const float* w1      = (const float*)d_in[14];
    const float* b1      = (const float*)d_in[15];
    const float* w2      = (const float*)d_in[16];
    const float* b2      = (const float*)d_in[17];
    const float* lnf_g   = (const float*)d_in[18];
    const float* lnf_b   = (const float*)d_in[19];
    const float* cls_w   = (const float*)d_in[20];
    const float* cls_b   = (const float*)d_in[21];
    float* out = (float*)d_out;

    __nv_bfloat16 *ph,*pl,*hh,*hl,*oh,*ol,*mh,*ml,*qkvh,*qkvl;
    __nv_bfloat16 *wqh,*wql,*woh,*wol,*w1h,*w1l,*w2h,*w2l,*pwh,*pwl;
    float *x,*clsb;
    cudaGetSymbolAddress((void**)&ph, g_ph);   cudaGetSymbolAddress((void**)&pl, g_pl);
    cudaGetSymbolAddress((void**)&hh, g_hh);   cudaGetSymbolAddress((void**)&hl, g_hl);
    cudaGetSymbolAddress((void**)&oh, g_oh);   cudaGetSymbolAddress((void**)&ol, g_ol);
    cudaGetSymbolAddress((void**)&mh, g_mh);   cudaGetSymbolAddress((void**)&ml, g_ml);
    cudaGetSymbolAddress((void**)&qkvh, g_qkvh); cudaGetSymbolAddress((void**)&qkvl, g_qkvl);
    cudaGetSymbolAddress((void**)&wqh, g_wqkvh); cudaGetSymbolAddress((void**)&wql, g_wqkvl);
    cudaGetSymbolAddress((void**)&woh, g_woh); cudaGetSymbolAddress((void**)&wol, g_wol);
    cudaGetSymbolAddress((void**)&w1h, g_w1h); cudaGetSymbolAddress((void**)&w1l, g_w1l);
    cudaGetSymbolAddress((void**)&w2h, g_w2h); cudaGetSymbolAddress((void**)&w2l, g_w2l);
    cudaGetSymbolAddress((void**)&pwh, g_pwh); cudaGetSymbolAddress((void**)&pwl, g_pwl);
    cudaGetSymbolAddress((void**)&x, g_x);     cudaGetSymbolAddress((void**)&clsb, g_cls);

    cudaFuncSetAttribute(gemm_hmma, cudaFuncAttributeMaxDynamicSharedMemorySize, GSMEM);
    cudaFuncSetAttribute(flash_kernel, cudaFuncAttributeMaxDynamicSharedMemorySize, FSMEM);

    // Weight conversion
    wconv_t_kernel<<<dim3(3*DD/32, DD/32, LLAY), dim3(32,8)>>>(wqkv, wqh, wql, DD, 3*DD);
    wconv_t_kernel<<<dim3(DD/32,   DD/32, LLAY), dim3(32,8)>>>(wo,   woh, wol, DD, DD);
    wconv_t_kernel<<<dim3(FF/32,   DD/32, LLAY), dim3(32,8)>>>(w1,   w1h, w1l, DD, FF);
    wconv_t_kernel<<<dim3(DD/32,   FF/32, LLAY), dim3(32,8)>>>(w2,   w2h, w2l, FF, DD);
    wconv_kernel<<<(DD*DD + 255)/256, 256>>>(patch_w, pwh, pwl, DD*DD);

    gather_kernel<<<(MPAT*DD + 255)/256, 256>>>(px, fix, ph, pl);
    cls_init_kernel<<<(BB*DD + 255)/256, 256>>>(cls_tok, pos_emb, x);
    gemm_hmma<<<dim3(DD/256, MPAT/128), 512, GSMEM>>>(
        ph, pl, pwh, pwl, x, nullptr, nullptr, MPAT, DD, DD, patch_b, pos_emb, EPI_PATCH);

    const int gM = (MROWS + 127) / 128;  // 50
    for (int l = 0; l < LLAY; l++) {
        ln_bf16_kernel<<<MROWS, 256>>>(x, hh, hl, ln1_g + l*DD, ln1_b + l*DD);
        gemm_hmma<<<dim3(3*DD/256, gM), 512, GSMEM>>>(
            hh, hl, wqh + (size_t)l*3*DD*DD, wql + (size_t)l*3*DD*DD,
            nullptr, qkvh, qkvl, MROWS, 3*DD, DD, bqkv + (size_t)l*3*DD, nullptr, EPI_QKV);
        flash_kernel<<<dim3(2, BHN), 256, FSMEM>>>(qkvh, qkvl, oh, ol);
        gemm_hmma<<<dim3(DD/256, gM), 512, GSMEM>>>(
            oh, ol, woh + (size_t)l*DD*DD, wol + (size_t)l*DD*DD,
            x, nullptr, nullptr, MROWS, DD, DD, bo + (size_t)l*DD, nullptr, EPI_RES);
        ln_bf16_kernel<<<MROWS, 256>>>(x, hh, hl, ln2_g + l*DD, ln2_b + l*DD);
        gemm_hmma<<<dim3(FF/256, gM), 512, GSMEM>>>(
            hh, hl, w1h + (size_t)l*FF*DD, w1l + (size_t)l*FF*DD,
            nullptr, mh, ml, MROWS, FF, DD, b1 + (size_t)l*FF, nullptr, EPI_GELU);
        gemm_hmma<<<dim3(DD/256, gM), 512, GSMEM>>>(
            mh, ml, w2h + (size_t)l*DD*FF, w2l + (size_t)l*DD*FF,
            x, nullptr, nullptr, MROWS, DD, FF, b2 + (size_t)l*DD, nullptr, EPI_RES);
    }

    ln_f32_kernel<<<BB, 256>>>(x, clsb, lnf_g, lnf_b, SS);
    cls_head_kernel<<<(BB*NLAB*32 + 255)/256, 256>>>(clsb, cls_w, cls_b, out);
}